// round 1
// baseline (speedup 1.0000x reference)
#include <cuda_runtime.h>
#include <math.h>

#define BSZ    2
#define SEQL   2048
#define DMODEL 1024
#define DINNER 2048
#define DSTATE 16
#define DTRANK 64
#define NTOK   (BSZ * SEQL)          // 4096
#define XPOUT  (DTRANK + 2 * DSTATE) // 96

// -------- scratch (static device globals; no runtime allocation) --------
__device__ float g_h  [(size_t)NTOK * DMODEL];      // 16 MB  normed hidden
__device__ float g_xz [(size_t)NTOK * 2 * DINNER];  // 64 MB  in_proj out (x | z)
__device__ float g_xc [(size_t)NTOK * DINNER];      // 32 MB  conv+silu out
__device__ float g_dbl[(size_t)NTOK * XPOUT];       // 1.5 MB x_proj out (dt_r|B|C)
__device__ float g_dt [(size_t)NTOK * DINNER];      // 32 MB  softplus(dt)
__device__ float g_y  [(size_t)NTOK * DINNER];      // 32 MB  scan output (fused gate)

// =======================================================================
// RMSNorm: one block per token row (1024 elems, 256 threads x float4)
// =======================================================================
__global__ void k_rmsnorm(const float* __restrict__ x, const float* __restrict__ w) {
    int row = blockIdx.x, tid = threadIdx.x;
    float4 v = ((const float4*)(x + (size_t)row * DMODEL))[tid];
    float ss = v.x * v.x + v.y * v.y + v.z * v.z + v.w * v.w;
    #pragma unroll
    for (int o = 16; o; o >>= 1) ss += __shfl_xor_sync(0xffffffffu, ss, o);
    __shared__ float sred[8];
    __shared__ float snorm;
    if ((tid & 31) == 0) sred[tid >> 5] = ss;
    __syncthreads();
    if (tid == 0) {
        float s = 0.f;
        #pragma unroll
        for (int i = 0; i < 8; i++) s += sred[i];
        snorm = rsqrtf(s * (1.0f / DMODEL) + 1e-5f);
    }
    __syncthreads();
    float r = snorm;
    float4 wv = ((const float4*)w)[tid];
    float4 o;
    o.x = v.x * r * wv.x; o.y = v.y * r * wv.y;
    o.z = v.z * r * wv.z; o.w = v.w * r * wv.w;
    ((float4*)(g_h + (size_t)row * DMODEL))[tid] = o;
}

// =======================================================================
// Generic NT SGEMM: C[M,N] = A[M,K(lda)] * B[N,K(ldb)]^T
// 128x128 block, BK=16, 256 threads, 8x8 per thread.
// epi: 0 = none, 1 = softplus(v + extra[n]), 2 = v + extra[m*ldc + n]
// =======================================================================
__global__ __launch_bounds__(256) void k_sgemm_nt(
    const float* __restrict__ A, int lda,
    const float* __restrict__ B, int ldb,
    float* __restrict__ C, int ldc,
    int M, int N, int K,
    int epi, const float* __restrict__ extra)
{
    __shared__ float As[16][132];
    __shared__ float Bs[16][132];
    int tid = threadIdx.x;
    int bm = blockIdx.y, bn = blockIdx.x;
    int lr = tid >> 2;            // 0..63
    int lc = (tid & 3) << 2;      // 0,4,8,12
    int tx = tid & 15, ty = tid >> 4;

    int am0 = bm * 128 + lr, am1 = am0 + 64;
    int bn0 = bn * 128 + lr, bn1 = bn0 + 64;
    const float* Ap0 = A + (size_t)am0 * lda + lc;
    const float* Ap1 = A + (size_t)am1 * lda + lc;
    const float* Bp0 = B + (size_t)bn0 * ldb + lc;
    const float* Bp1 = B + (size_t)bn1 * ldb + lc;
    bool va0 = am0 < M, va1 = am1 < M, vb0 = bn0 < N, vb1 = bn1 < N;

    float acc[8][8];
    #pragma unroll
    for (int i = 0; i < 8; i++)
        #pragma unroll
        for (int j = 0; j < 8; j++) acc[i][j] = 0.f;

    const float4 z4 = make_float4(0.f, 0.f, 0.f, 0.f);
    for (int k0 = 0; k0 < K; k0 += 16) {
        float4 a0 = va0 ? *(const float4*)(Ap0 + k0) : z4;
        float4 a1 = va1 ? *(const float4*)(Ap1 + k0) : z4;
        float4 b0 = vb0 ? *(const float4*)(Bp0 + k0) : z4;
        float4 b1 = vb1 ? *(const float4*)(Bp1 + k0) : z4;
        __syncthreads();
        As[lc + 0][lr] = a0.x; As[lc + 1][lr] = a0.y;
        As[lc + 2][lr] = a0.z; As[lc + 3][lr] = a0.w;
        As[lc + 0][lr + 64] = a1.x; As[lc + 1][lr + 64] = a1.y;
        As[lc + 2][lr + 64] = a1.z; As[lc + 3][lr + 64] = a1.w;
        Bs[lc + 0][lr] = b0.x; Bs[lc + 1][lr] = b0.y;
        Bs[lc + 2][lr] = b0.z; Bs[lc + 3][lr] = b0.w;
        Bs[lc + 0][lr + 64] = b1.x; Bs[lc + 1][lr + 64] = b1.y;
        Bs[lc + 2][lr + 64] = b1.z; Bs[lc + 3][lr + 64] = b1.w;
        __syncthreads();
        #pragma unroll
        for (int kk = 0; kk < 16; kk++) {
            float4 ra0 = *(const float4*)&As[kk][ty * 8];
            float4 ra1 = *(const float4*)&As[kk][ty * 8 + 4];
            float4 rb0 = *(const float4*)&Bs[kk][tx * 8];
            float4 rb1 = *(const float4*)&Bs[kk][tx * 8 + 4];
            float ra[8] = {ra0.x, ra0.y, ra0.z, ra0.w, ra1.x, ra1.y, ra1.z, ra1.w};
            float rb[8] = {rb0.x, rb0.y, rb0.z, rb0.w, rb1.x, rb1.y, rb1.z, rb1.w};
            #pragma unroll
            for (int i = 0; i < 8; i++)
                #pragma unroll
                for (int j = 0; j < 8; j++)
                    acc[i][j] = fmaf(ra[i], rb[j], acc[i][j]);
        }
    }

    #pragma unroll
    for (int i = 0; i < 8; i++) {
        int m = bm * 128 + ty * 8 + i;
        if (m >= M) continue;
        #pragma unroll
        for (int j = 0; j < 8; j++) {
            int n = bn * 128 + tx * 8 + j;
            if (n >= N) continue;
            float v = acc[i][j];
            if (epi == 1) {
                v += extra[n];
                v = (v > 20.f) ? v : log1pf(expf(v));     // softplus
            } else if (epi == 2) {
                v += extra[(size_t)m * ldc + n];          // residual
            }
            C[(size_t)m * ldc + n] = v;
        }
    }
}

// =======================================================================
// Causal depthwise conv (width 4) + SiLU.  x lives in g_xz cols [0,2048)
// =======================================================================
__global__ void k_conv_silu(const float* __restrict__ cw, const float* __restrict__ cb) {
    size_t idx = (size_t)blockIdx.x * blockDim.x + threadIdx.x;
    if (idx >= (size_t)NTOK * DINNER) return;
    int d = (int)(idx & (DINNER - 1));
    int t = (int)((idx >> 11) & (SEQL - 1));
    int b = (int)(idx >> 22);
    const float* xp = g_xz + (size_t)b * SEQL * (2 * DINNER) + d;
    float acc = cb[d];
    #pragma unroll
    for (int j = 0; j < 4; j++) {
        int tt = t - 3 + j;
        if (tt >= 0)
            acc = fmaf(__ldg(cw + d * 4 + j), xp[(size_t)tt * (2 * DINNER)], acc);
    }
    g_xc[idx] = acc / (1.f + expf(-acc));   // silu
}

// =======================================================================
// Selective scan. 16 lanes per (b,d) channel: lane = state index n.
// Recurrence h = h*exp(dt*A_n) + dt*x*B_n ; y = sum_n h*C_n
// Fused epilogue: y = (y + x*D) * silu(z)
// =======================================================================
__global__ __launch_bounds__(256) void k_scan(const float* __restrict__ alog,
                                              const float* __restrict__ Dp) {
    int g    = blockIdx.x * 16 + (threadIdx.x >> 4);   // (b,d) group, 4096 total
    int lane = threadIdx.x & 15;
    int b = g >> 11;
    int d = g & (DINNER - 1);

    float A  = -expf(alog[d * DSTATE + lane]);
    float Dd = Dp[d];
    float h  = 0.f;

    const float* xc_p = g_xc  + (size_t)b * SEQL * DINNER + d;
    const float* dt_p = g_dt  + (size_t)b * SEQL * DINNER + d;
    const float* bl_p = g_dbl + (size_t)b * SEQL * XPOUT;
    const float* z_p  = g_xz  + (size_t)b * SEQL * (2 * DINNER) + DINNER + d;
    float*       y_p  = g_y   + (size_t)b * SEQL * DINNER + d;

    for (int t = 0; t < SEQL; t++) {
        float x  = __ldg(xc_p + (size_t)t * DINNER);
        float dt = __ldg(dt_p + (size_t)t * DINNER);
        float Bn = __ldg(bl_p + (size_t)t * XPOUT + DTRANK + lane);
        float Cn = __ldg(bl_p + (size_t)t * XPOUT + DTRANK + DSTATE + lane);
        float dA = __expf(dt * A);
        h = fmaf(h, dA, dt * x * Bn);
        float v = h * Cn;
        v += __shfl_xor_sync(0xffffffffu, v, 8, 16);
        v += __shfl_xor_sync(0xffffffffu, v, 4, 16);
        v += __shfl_xor_sync(0xffffffffu, v, 2, 16);
        v += __shfl_xor_sync(0xffffffffu, v, 1, 16);
        if (lane == 0) {
            float z   = __ldg(z_p + (size_t)t * (2 * DINNER));
            float sig = 1.f / (1.f + __expf(-z));
            y_p[(size_t)t * DINNER] = (v + x * Dd) * (z * sig);
        }
    }
}

// =======================================================================
extern "C" void kernel_launch(void* const* d_in, const int* in_sizes, int n_in,
                              void* d_out, int out_size) {
    const float* hs   = (const float*)d_in[0];   // hidden_states (2,2048,1024)
    const float* nw   = (const float*)d_in[1];   // norm_weight   (1024)
    const float* inw  = (const float*)d_in[2];   // in_proj_w     (4096,1024)
    const float* cw   = (const float*)d_in[3];   // conv_w        (2048,1,4)
    const float* cb   = (const float*)d_in[4];   // conv_b        (2048)
    const float* xpw  = (const float*)d_in[5];   // x_proj_w      (96,2048)
    const float* dtw  = (const float*)d_in[6];   // dt_proj_w     (2048,64)
    const float* dtb  = (const float*)d_in[7];   // dt_proj_b     (2048)
    const float* alog = (const float*)d_in[8];   // A_log         (2048,16)
    const float* Dp   = (const float*)d_in[9];   // D             (2048)
    const float* ow   = (const float*)d_in[10];  // out_proj_w    (1024,2048)
    float* out = (float*)d_out;                  // (2,2048,1024)

    float *p_h, *p_xz, *p_xc, *p_dbl, *p_dt, *p_y;
    cudaGetSymbolAddress((void**)&p_h,   g_h);
    cudaGetSymbolAddress((void**)&p_xz,  g_xz);
    cudaGetSymbolAddress((void**)&p_xc,  g_xc);
    cudaGetSymbolAddress((void**)&p_dbl, g_dbl);
    cudaGetSymbolAddress((void**)&p_dt,  g_dt);
    cudaGetSymbolAddress((void**)&p_y,   g_y);

    // 1. RMSNorm
    k_rmsnorm<<<NTOK, 256>>>(hs, nw);

    // 2. xz = h @ in_proj_w^T   (4096 x 4096, K=1024)
    k_sgemm_nt<<<dim3(32, 32), 256>>>(p_h, DMODEL, inw, DMODEL,
                                      p_xz, 2 * DINNER,
                                      NTOK, 2 * DINNER, DMODEL, 0, nullptr);

    // 3. depthwise conv + SiLU
    k_conv_silu<<<(NTOK * DINNER) / 256, 256>>>(cw, cb);

    // 4. dbl = xc @ x_proj_w^T  (4096 x 96, K=2048)
    k_sgemm_nt<<<dim3(1, 32), 256>>>(p_xc, DINNER, xpw, DINNER,
                                     p_dbl, XPOUT,
                                     NTOK, XPOUT, DINNER, 0, nullptr);

    // 5. dt = softplus(dt_r @ dt_proj_w^T + b)  (4096 x 2048, K=64, lda=96)
    k_sgemm_nt<<<dim3(16, 32), 256>>>(p_dbl, XPOUT, dtw, DTRANK,
                                      p_dt, DINNER,
                                      NTOK, DINNER, DTRANK, 1, dtb);

    // 6. selective scan + gating
    k_scan<<<256, 256>>>(alog, Dp);

    // 7. out = y @ out_proj_w^T + residual  (4096 x 1024, K=2048)
    k_sgemm_nt<<<dim3(8, 32), 256>>>(p_y, DINNER, ow, DINNER,
                                     out, DMODEL,
                                     NTOK, DMODEL, DINNER, 2, hs);
}

// round 2
// speedup vs baseline: 1.8738x; 1.8738x over previous
#include <cuda_runtime.h>
#include <math.h>
#include <stdint.h>

#define BSZ    2
#define SEQL   2048
#define DMODEL 1024
#define DINNER 2048
#define DSTATE 16
#define DTRANK 64
#define NTOK   (BSZ * SEQL)          // 4096
#define XPOUT  (DTRANK + 2 * DSTATE) // 96

// -------- scratch (static device globals; no runtime allocation) --------
__device__ float g_h  [(size_t)NTOK * DMODEL];      // normed hidden
__device__ float g_xz [(size_t)NTOK * 2 * DINNER];  // in_proj out (x | z)
__device__ float g_xc [(size_t)NTOK * DINNER];      // conv+silu out
__device__ float g_dbl[(size_t)NTOK * XPOUT];       // x_proj out (dt_r|B|C)
__device__ float g_dt [(size_t)NTOK * DINNER];      // softplus(dt)
__device__ float g_y  [(size_t)NTOK * DINNER];      // scan output (gated)

// =======================================================================
// helpers: tf32 convert + m16n8k8 tf32 MMA
// =======================================================================
__device__ __forceinline__ uint32_t f2tf(float x) {
    uint32_t u; asm("cvt.rna.tf32.f32 %0, %1;" : "=r"(u) : "f"(x)); return u;
}
__device__ __forceinline__ void mma_tf32(float* c, const uint32_t* a, const uint32_t* b) {
    asm volatile(
        "mma.sync.aligned.m16n8k8.row.col.f32.tf32.tf32.f32 "
        "{%0,%1,%2,%3}, {%4,%5,%6,%7}, {%8,%9}, {%0,%1,%2,%3};"
        : "+f"(c[0]), "+f"(c[1]), "+f"(c[2]), "+f"(c[3])
        : "r"(a[0]), "r"(a[1]), "r"(a[2]), "r"(a[3]), "r"(b[0]), "r"(b[1]));
}

template<int BK, int CNT, int THREADS>
__device__ __forceinline__ void ld_tile(float4* r, const float* __restrict__ G,
                                        int ld, int row0, int kb, int tid) {
    #pragma unroll
    for (int i = 0; i < CNT; i++) {
        int e = (tid + i * THREADS) * 4;
        int row = e / BK, col = e % BK;
        r[i] = *(const float4*)(G + (size_t)(row0 + row) * ld + kb * BK + col);
    }
}
template<int BK, int LDS, int CNT, int THREADS>
__device__ __forceinline__ void st_tile(uint32_t* S, const float4* r, int tid) {
    #pragma unroll
    for (int i = 0; i < CNT; i++) {
        int e = (tid + i * THREADS) * 4;
        int row = e / BK, col = e % BK;
        uint4 v = make_uint4(f2tf(r[i].x), f2tf(r[i].y), f2tf(r[i].z), f2tf(r[i].w));
        *(uint4*)&S[row * LDS + col] = v;
    }
}

// =======================================================================
// NT GEMM on tf32 tensor cores: C[M,N] = A[M,K]·B[N,K]^T
// All dims must divide the tile config (true for every call site here).
// EPI: 0=none, 1=softplus(v+extra[n]), 2=v+extra[m*ldc+n]
// =======================================================================
template<int BM, int BN, int WARPS_M, int WARPS_N, int EPI>
__global__ void __launch_bounds__(WARPS_M * WARPS_N * 32)
k_mma_nt(const float* __restrict__ A, int lda,
         const float* __restrict__ B, int ldb,
         float* __restrict__ C, int ldc,
         int K, const float* __restrict__ extra)
{
    constexpr int BK = 16, LDS = BK + 4;
    constexpr int THREADS = WARPS_M * WARPS_N * 32;
    constexpr int WM = BM / WARPS_M, WN = BN / WARPS_N;
    constexpr int MT = WM / 16, NT = WN / 8;
    constexpr int AF = (BM * BK) / (THREADS * 4);
    constexpr int BF = (BN * BK) / (THREADS * 4);

    __shared__ uint32_t As[2][BM * LDS];
    __shared__ uint32_t Bs[2][BN * LDS];

    int tid = threadIdx.x, lane = tid & 31, wid = tid >> 5;
    int wm = wid % WARPS_M, wn = wid / WARPS_M;
    int bm0 = blockIdx.y * BM, bn0 = blockIdx.x * BN;

    float acc[MT][NT][4];
    #pragma unroll
    for (int mt = 0; mt < MT; mt++)
        #pragma unroll
        for (int nt = 0; nt < NT; nt++)
            #pragma unroll
            for (int i = 0; i < 4; i++) acc[mt][nt][i] = 0.f;

    float4 ra[AF], rb[BF];
    ld_tile<BK, AF, THREADS>(ra, A, lda, bm0, 0, tid);
    ld_tile<BK, BF, THREADS>(rb, B, ldb, bn0, 0, tid);
    st_tile<BK, LDS, AF, THREADS>(As[0], ra, tid);
    st_tile<BK, LDS, BF, THREADS>(Bs[0], rb, tid);
    __syncthreads();

    int nkb = K / BK;
    for (int kb = 0; kb < nkb; kb++) {
        int cur = kb & 1;
        if (kb + 1 < nkb) {
            ld_tile<BK, AF, THREADS>(ra, A, lda, bm0, kb + 1, tid);
            ld_tile<BK, BF, THREADS>(rb, B, ldb, bn0, kb + 1, tid);
        }
        const uint32_t* Ab = As[cur];
        const uint32_t* Bb = Bs[cur];
        #pragma unroll
        for (int ks = 0; ks < 2; ks++) {
            uint32_t af[MT][4], bf[NT][2];
            #pragma unroll
            for (int mt = 0; mt < MT; mt++) {
                int r = wm * WM + mt * 16 + (lane >> 2);
                int c = ks * 8 + (lane & 3);
                af[mt][0] = Ab[r * LDS + c];
                af[mt][1] = Ab[(r + 8) * LDS + c];
                af[mt][2] = Ab[r * LDS + c + 4];
                af[mt][3] = Ab[(r + 8) * LDS + c + 4];
            }
            #pragma unroll
            for (int nt = 0; nt < NT; nt++) {
                int r = wn * WN + nt * 8 + (lane >> 2);
                int c = ks * 8 + (lane & 3);
                bf[nt][0] = Bb[r * LDS + c];
                bf[nt][1] = Bb[r * LDS + c + 4];
            }
            #pragma unroll
            for (int mt = 0; mt < MT; mt++)
                #pragma unroll
                for (int nt = 0; nt < NT; nt++)
                    mma_tf32(acc[mt][nt], af[mt], bf[nt]);
        }
        if (kb + 1 < nkb) {
            st_tile<BK, LDS, AF, THREADS>(As[cur ^ 1], ra, tid);
            st_tile<BK, LDS, BF, THREADS>(Bs[cur ^ 1], rb, tid);
        }
        __syncthreads();
    }

    // epilogue
    #pragma unroll
    for (int mt = 0; mt < MT; mt++) {
        int r0 = bm0 + wm * WM + mt * 16 + (lane >> 2);
        #pragma unroll
        for (int nt = 0; nt < NT; nt++) {
            int c0 = bn0 + wn * WN + nt * 8 + ((lane & 3) << 1);
            #pragma unroll
            for (int q = 0; q < 4; q++) {
                int m = r0 + (q >> 1) * 8;
                int n = c0 + (q & 1);
                float v = acc[mt][nt][q];
                if (EPI == 1) {
                    v += extra[n];
                    v = (v > 20.f) ? v : log1pf(expf(v));
                } else if (EPI == 2) {
                    v += extra[(size_t)m * ldc + n];
                }
                C[(size_t)m * ldc + n] = v;
            }
        }
    }
}

// =======================================================================
// RMSNorm: one block per token row (1024 elems, 256 threads x float4)
// =======================================================================
__global__ void k_rmsnorm(const float* __restrict__ x, const float* __restrict__ w) {
    int row = blockIdx.x, tid = threadIdx.x;
    float4 v = ((const float4*)(x + (size_t)row * DMODEL))[tid];
    float ss = v.x * v.x + v.y * v.y + v.z * v.z + v.w * v.w;
    #pragma unroll
    for (int o = 16; o; o >>= 1) ss += __shfl_xor_sync(0xffffffffu, ss, o);
    __shared__ float sred[8];
    __shared__ float snorm;
    if ((tid & 31) == 0) sred[tid >> 5] = ss;
    __syncthreads();
    if (tid == 0) {
        float s = 0.f;
        #pragma unroll
        for (int i = 0; i < 8; i++) s += sred[i];
        snorm = rsqrtf(s * (1.0f / DMODEL) + 1e-5f);
    }
    __syncthreads();
    float r = snorm;
    float4 wv = ((const float4*)w)[tid];
    float4 o;
    o.x = v.x * r * wv.x; o.y = v.y * r * wv.y;
    o.z = v.z * r * wv.z; o.w = v.w * r * wv.w;
    ((float4*)(g_h + (size_t)row * DMODEL))[tid] = o;
}

// =======================================================================
// Causal depthwise conv (width 4) + SiLU.  x lives in g_xz cols [0,2048)
// =======================================================================
__global__ void k_conv_silu(const float* __restrict__ cw, const float* __restrict__ cb) {
    size_t idx = (size_t)blockIdx.x * blockDim.x + threadIdx.x;
    if (idx >= (size_t)NTOK * DINNER) return;
    int d = (int)(idx & (DINNER - 1));
    int t = (int)((idx >> 11) & (SEQL - 1));
    int b = (int)(idx >> 22);
    const float* xp = g_xz + (size_t)b * SEQL * (2 * DINNER) + d;
    float acc = cb[d];
    #pragma unroll
    for (int j = 0; j < 4; j++) {
        int tt = t - 3 + j;
        if (tt >= 0)
            acc = fmaf(__ldg(cw + d * 4 + j), xp[(size_t)tt * (2 * DINNER)], acc);
    }
    g_xc[idx] = acc / (1.f + expf(-acc));   // silu
}

// =======================================================================
// Selective scan. 16 lanes per (b,d) channel: lane = state index n.
// =======================================================================
__global__ __launch_bounds__(256) void k_scan(const float* __restrict__ alog,
                                              const float* __restrict__ Dp) {
    int g    = blockIdx.x * 16 + (threadIdx.x >> 4);
    int lane = threadIdx.x & 15;
    int b = g >> 11;
    int d = g & (DINNER - 1);

    float A  = -expf(alog[d * DSTATE + lane]);
    float Dd = Dp[d];
    float h  = 0.f;

    const float* xc_p = g_xc  + (size_t)b * SEQL * DINNER + d;
    const float* dt_p = g_dt  + (size_t)b * SEQL * DINNER + d;
    const float* bl_p = g_dbl + (size_t)b * SEQL * XPOUT;
    const float* z_p  = g_xz  + (size_t)b * SEQL * (2 * DINNER) + DINNER + d;
    float*       y_p  = g_y   + (size_t)b * SEQL * DINNER + d;

    for (int t = 0; t < SEQL; t++) {
        float x  = __ldg(xc_p + (size_t)t * DINNER);
        float dt = __ldg(dt_p + (size_t)t * DINNER);
        float Bn = __ldg(bl_p + (size_t)t * XPOUT + DTRANK + lane);
        float Cn = __ldg(bl_p + (size_t)t * XPOUT + DTRANK + DSTATE + lane);
        float dA = __expf(dt * A);
        h = fmaf(h, dA, dt * x * Bn);
        float v = h * Cn;
        v += __shfl_xor_sync(0xffffffffu, v, 8, 16);
        v += __shfl_xor_sync(0xffffffffu, v, 4, 16);
        v += __shfl_xor_sync(0xffffffffu, v, 2, 16);
        v += __shfl_xor_sync(0xffffffffu, v, 1, 16);
        if (lane == 0) {
            float z   = __ldg(z_p + (size_t)t * (2 * DINNER));
            float sig = 1.f / (1.f + __expf(-z));
            y_p[(size_t)t * DINNER] = (v + x * Dd) * (z * sig);
        }
    }
}

// =======================================================================
extern "C" void kernel_launch(void* const* d_in, const int* in_sizes, int n_in,
                              void* d_out, int out_size) {
    const float* hs   = (const float*)d_in[0];
    const float* nw   = (const float*)d_in[1];
    const float* inw  = (const float*)d_in[2];
    const float* cw   = (const float*)d_in[3];
    const float* cb   = (const float*)d_in[4];
    const float* xpw  = (const float*)d_in[5];
    const float* dtw  = (const float*)d_in[6];
    const float* dtb  = (const float*)d_in[7];
    const float* alog = (const float*)d_in[8];
    const float* Dp   = (const float*)d_in[9];
    const float* ow   = (const float*)d_in[10];
    float* out = (float*)d_out;

    float *p_h, *p_xz, *p_xc, *p_dbl, *p_dt, *p_y;
    cudaGetSymbolAddress((void**)&p_h,   g_h);
    cudaGetSymbolAddress((void**)&p_xz,  g_xz);
    cudaGetSymbolAddress((void**)&p_xc,  g_xc);
    cudaGetSymbolAddress((void**)&p_dbl, g_dbl);
    cudaGetSymbolAddress((void**)&p_dt,  g_dt);
    cudaGetSymbolAddress((void**)&p_y,   g_y);

    // 1. RMSNorm
    k_rmsnorm<<<NTOK, 256>>>(hs, nw);

    // 2. xz = h @ in_proj_w^T   (4096 x 4096, K=1024)
    k_mma_nt<128, 128, 4, 4, 0><<<dim3(32, 32), 512>>>(
        p_h, DMODEL, inw, DMODEL, p_xz, 2 * DINNER, DMODEL, nullptr);

    // 3. depthwise conv + SiLU
    k_conv_silu<<<(NTOK * DINNER) / 256, 256>>>(cw, cb);

    // 4. dbl = xc @ x_proj_w^T  (4096 x 96, K=2048)
    k_mma_nt<64, 32, 2, 2, 0><<<dim3(3, 64), 128>>>(
        p_xc, DINNER, xpw, DINNER, p_dbl, XPOUT, DINNER, nullptr);

    // 5. dt = softplus(dt_r @ dt_proj_w^T + b)  (4096 x 2048, K=64, lda=96)
    k_mma_nt<128, 128, 4, 4, 1><<<dim3(16, 32), 512>>>(
        p_dbl, XPOUT, dtw, DTRANK, p_dt, DINNER, DTRANK, dtb);

    // 6. selective scan + gating
    k_scan<<<256, 256>>>(alog, Dp);

    // 7. out = y @ out_proj_w^T + residual  (4096 x 1024, K=2048)
    k_mma_nt<128, 128, 4, 4, 2><<<dim3(8, 32), 512>>>(
        p_y, DINNER, ow, DINNER, out, DMODEL, DINNER, hs);
}

// round 3
// speedup vs baseline: 2.1763x; 1.1615x over previous
#include <cuda_runtime.h>
#include <cuda_bf16.h>
#include <math.h>
#include <stdint.h>

#define BSZ    2
#define SEQL   2048
#define DMODEL 1024
#define DINNER 2048
#define DSTATE 16
#define DTRANK 64
#define NTOK   (BSZ * SEQL)          // 4096
#define XPOUT  (DTRANK + 2 * DSTATE) // 96

// -------- scratch (static device globals; no runtime allocation) --------
__device__ float g_xz [(size_t)NTOK * 2 * DINNER];  // in_proj out (x | z) fp32
__device__ float g_xc [(size_t)NTOK * DINNER];      // conv+silu out fp32 (scan)
__device__ float g_dbl[(size_t)NTOK * XPOUT];       // x_proj out fp32 (scan B,C)
__device__ float g_dt [(size_t)NTOK * DINNER];      // softplus(dt) fp32 (scan)

__device__ __nv_bfloat16 g_hb  [(size_t)NTOK * DMODEL];   // rmsnorm out (A of in_proj)
__device__ __nv_bfloat16 g_xcb [(size_t)NTOK * DINNER];   // conv out (A of x_proj)
__device__ __nv_bfloat16 g_dblb[(size_t)NTOK * XPOUT];    // x_proj out (A of dt_proj)
__device__ __nv_bfloat16 g_yb  [(size_t)NTOK * DINNER];   // scan out (A of out_proj)
__device__ __nv_bfloat16 g_inwb[(size_t)2 * DINNER * DMODEL];
__device__ __nv_bfloat16 g_xpwb[(size_t)XPOUT * DINNER];
__device__ __nv_bfloat16 g_dtwb[(size_t)DINNER * DTRANK];
__device__ __nv_bfloat16 g_owb [(size_t)DMODEL * DINNER];

// =======================================================================
// helpers
// =======================================================================
__device__ __forceinline__ void cp_async16(void* smem_dst, const void* gmem_src) {
    uint32_t s = (uint32_t)__cvta_generic_to_shared(smem_dst);
    asm volatile("cp.async.cg.shared.global [%0], [%1], 16;\n" :: "r"(s), "l"(gmem_src));
}
__device__ __forceinline__ void cp_commit() {
    asm volatile("cp.async.commit_group;\n");
}
template<int N> __device__ __forceinline__ void cp_wait() {
    asm volatile("cp.async.wait_group %0;\n" :: "n"(N));
}
__device__ __forceinline__ void mma_bf16(float* c, const uint32_t* a, const uint32_t* b) {
    asm volatile(
        "mma.sync.aligned.m16n8k16.row.col.f32.bf16.bf16.f32 "
        "{%0,%1,%2,%3}, {%4,%5,%6,%7}, {%8,%9}, {%0,%1,%2,%3};"
        : "+f"(c[0]), "+f"(c[1]), "+f"(c[2]), "+f"(c[3])
        : "r"(a[0]), "r"(a[1]), "r"(a[2]), "r"(a[3]), "r"(b[0]), "r"(b[1]));
}

// fp32 -> bf16 conversion (weights), grid-stride, 4 per thread
__global__ void k_f2bf(const float* __restrict__ src, __nv_bfloat16* __restrict__ dst, int n) {
    int i = (blockIdx.x * blockDim.x + threadIdx.x) * 4;
    if (i + 3 < n) {
        float4 v = *(const float4*)(src + i);
        dst[i]     = __float2bfloat16(v.x);
        dst[i + 1] = __float2bfloat16(v.y);
        dst[i + 2] = __float2bfloat16(v.z);
        dst[i + 3] = __float2bfloat16(v.w);
    } else {
        for (int j = i; j < n; j++) dst[j] = __float2bfloat16(src[j]);
    }
}

// =======================================================================
// NT GEMM, bf16 tensor cores, cp.async double-buffered, BK=32.
// C[M,N] = A[M,K]·B[N,K]^T.  All dims divide the tile config.
// EPI: 0=none, 1=softplus(v+extra[n]), 2=v+extra[m*ldc+n]
// WB: also write bf16 copy to Cb
// =======================================================================
template<int BM, int BN, int WARPS_M, int WARPS_N, int EPI, bool WB>
__global__ void __launch_bounds__(WARPS_M * WARPS_N * 32)
k_bmma_nt(const __nv_bfloat16* __restrict__ A, int lda,
          const __nv_bfloat16* __restrict__ B, int ldb,
          float* __restrict__ C, int ldc, int K,
          const float* __restrict__ extra, __nv_bfloat16* __restrict__ Cb)
{
    constexpr int BK = 32, LDS = 40;                 // halves; 20 words/row
    constexpr int THREADS = WARPS_M * WARPS_N * 32;
    constexpr int WM = BM / WARPS_M, WN = BN / WARPS_N;
    constexpr int MT = WM / 16, NT = WN / 8;
    constexpr int AITER = BM * BK / (THREADS * 8);
    constexpr int BITER = BN * BK / (THREADS * 8);

    __shared__ __nv_bfloat16 As[2][BM * LDS];
    __shared__ __nv_bfloat16 Bs[2][BN * LDS];

    int tid = threadIdx.x, lane = tid & 31, wid = tid >> 5;
    int wm = wid % WARPS_M, wn = wid / WARPS_M;
    int bm0 = blockIdx.y * BM, bn0 = blockIdx.x * BN;

    float acc[MT][NT][4];
    #pragma unroll
    for (int mt = 0; mt < MT; mt++)
        #pragma unroll
        for (int nt = 0; nt < NT; nt++)
            #pragma unroll
            for (int i = 0; i < 4; i++) acc[mt][nt][i] = 0.f;

    auto issue = [&](int kb, int buf) {
        #pragma unroll
        for (int i = 0; i < AITER; i++) {
            int e = tid + i * THREADS;
            int row = e >> 2, col = (e & 3) * 8;
            cp_async16(&As[buf][row * LDS + col],
                       A + (size_t)(bm0 + row) * lda + kb * BK + col);
        }
        #pragma unroll
        for (int i = 0; i < BITER; i++) {
            int e = tid + i * THREADS;
            int row = e >> 2, col = (e & 3) * 8;
            cp_async16(&Bs[buf][row * LDS + col],
                       B + (size_t)(bn0 + row) * ldb + kb * BK + col);
        }
        cp_commit();
    };

    int nkb = K / BK;
    issue(0, 0);

    for (int kb = 0; kb < nkb; kb++) {
        int buf = kb & 1;
        if (kb + 1 < nkb) {
            issue(kb + 1, buf ^ 1);
            cp_wait<1>();
        } else {
            cp_wait<0>();
        }
        __syncthreads();

        const uint32_t* Aw = (const uint32_t*)As[buf];
        const uint32_t* Bw = (const uint32_t*)Bs[buf];
        #pragma unroll
        for (int ks = 0; ks < 2; ks++) {
            int k0 = ks * 8 + (lane & 3);            // word offset within row
            uint32_t af[MT][4], bfr[NT][2];
            #pragma unroll
            for (int mt = 0; mt < MT; mt++) {
                int r = wm * WM + mt * 16 + (lane >> 2);
                af[mt][0] = Aw[r * (LDS / 2) + k0];
                af[mt][1] = Aw[(r + 8) * (LDS / 2) + k0];
                af[mt][2] = Aw[r * (LDS / 2) + k0 + 4];
                af[mt][3] = Aw[(r + 8) * (LDS / 2) + k0 + 4];
            }
            #pragma unroll
            for (int nt = 0; nt < NT; nt++) {
                int n = wn * WN + nt * 8 + (lane >> 2);
                bfr[nt][0] = Bw[n * (LDS / 2) + k0];
                bfr[nt][1] = Bw[n * (LDS / 2) + k0 + 4];
            }
            #pragma unroll
            for (int mt = 0; mt < MT; mt++)
                #pragma unroll
                for (int nt = 0; nt < NT; nt++)
                    mma_bf16(acc[mt][nt], af[mt], bfr[nt]);
        }
        __syncthreads();
    }

    // epilogue
    #pragma unroll
    for (int mt = 0; mt < MT; mt++) {
        int r0 = bm0 + wm * WM + mt * 16 + (lane >> 2);
        #pragma unroll
        for (int nt = 0; nt < NT; nt++) {
            int c0 = bn0 + wn * WN + nt * 8 + ((lane & 3) << 1);
            #pragma unroll
            for (int q = 0; q < 4; q++) {
                int m = r0 + (q >> 1) * 8;
                int n = c0 + (q & 1);
                float v = acc[mt][nt][q];
                if (EPI == 1) {
                    v += extra[n];
                    v = (v > 20.f) ? v : log1pf(expf(v));
                } else if (EPI == 2) {
                    v += extra[(size_t)m * ldc + n];
                }
                C[(size_t)m * ldc + n] = v;
                if (WB) Cb[(size_t)m * ldc + n] = __float2bfloat16(v);
            }
        }
    }
}

// =======================================================================
// RMSNorm -> bf16 output (A operand of in_proj)
// =======================================================================
__global__ void k_rmsnorm(const float* __restrict__ x, const float* __restrict__ w) {
    int row = blockIdx.x, tid = threadIdx.x;
    float4 v = ((const float4*)(x + (size_t)row * DMODEL))[tid];
    float ss = v.x * v.x + v.y * v.y + v.z * v.z + v.w * v.w;
    #pragma unroll
    for (int o = 16; o; o >>= 1) ss += __shfl_xor_sync(0xffffffffu, ss, o);
    __shared__ float sred[8];
    __shared__ float snorm;
    if ((tid & 31) == 0) sred[tid >> 5] = ss;
    __syncthreads();
    if (tid == 0) {
        float s = 0.f;
        #pragma unroll
        for (int i = 0; i < 8; i++) s += sred[i];
        snorm = rsqrtf(s * (1.0f / DMODEL) + 1e-5f);
    }
    __syncthreads();
    float r = snorm;
    float4 wv = ((const float4*)w)[tid];
    __nv_bfloat162 o0 = make_bfloat162(__float2bfloat16(v.x * r * wv.x),
                                       __float2bfloat16(v.y * r * wv.y));
    __nv_bfloat162 o1 = make_bfloat162(__float2bfloat16(v.z * r * wv.z),
                                       __float2bfloat16(v.w * r * wv.w));
    __nv_bfloat162* dst = (__nv_bfloat162*)(g_hb + (size_t)row * DMODEL) + tid * 2;
    dst[0] = o0; dst[1] = o1;
}

// =======================================================================
// Causal depthwise conv (width 4) + SiLU -> fp32 (scan) + bf16 (x_proj A)
// =======================================================================
__global__ void k_conv_silu(const float* __restrict__ cw, const float* __restrict__ cb) {
    size_t idx = (size_t)blockIdx.x * blockDim.x + threadIdx.x;
    if (idx >= (size_t)NTOK * DINNER) return;
    int d = (int)(idx & (DINNER - 1));
    int t = (int)((idx >> 11) & (SEQL - 1));
    int b = (int)(idx >> 22);
    const float* xp = g_xz + (size_t)b * SEQL * (2 * DINNER) + d;
    float acc = cb[d];
    #pragma unroll
    for (int j = 0; j < 4; j++) {
        int tt = t - 3 + j;
        if (tt >= 0)
            acc = fmaf(__ldg(cw + d * 4 + j), xp[(size_t)tt * (2 * DINNER)], acc);
    }
    float s = acc / (1.f + expf(-acc));
    g_xc[idx]  = s;
    g_xcb[idx] = __float2bfloat16(s);
}

// =======================================================================
// Selective scan. 16 lanes per (b,d) channel; writes bf16 y (out_proj A)
// =======================================================================
__global__ __launch_bounds__(256) void k_scan(const float* __restrict__ alog,
                                              const float* __restrict__ Dp) {
    int g    = blockIdx.x * 16 + (threadIdx.x >> 4);
    int lane = threadIdx.x & 15;
    int b = g >> 11;
    int d = g & (DINNER - 1);

    float A  = -expf(alog[d * DSTATE + lane]);
    float Dd = Dp[d];
    float h  = 0.f;

    const float* xc_p = g_xc  + (size_t)b * SEQL * DINNER + d;
    const float* dt_p = g_dt  + (size_t)b * SEQL * DINNER + d;
    const float* bl_p = g_dbl + (size_t)b * SEQL * XPOUT;
    const float* z_p  = g_xz  + (size_t)b * SEQL * (2 * DINNER) + DINNER + d;
    __nv_bfloat16* y_p = g_yb + (size_t)b * SEQL * DINNER + d;

    for (int t = 0; t < SEQL; t++) {
        float x  = __ldg(xc_p + (size_t)t * DINNER);
        float dt = __ldg(dt_p + (size_t)t * DINNER);
        float Bn = __ldg(bl_p + (size_t)t * XPOUT + DTRANK + lane);
        float Cn = __ldg(bl_p + (size_t)t * XPOUT + DTRANK + DSTATE + lane);
        float dA = __expf(dt * A);
        h = fmaf(h, dA, dt * x * Bn);
        float v = h * Cn;
        v += __shfl_xor_sync(0xffffffffu, v, 8, 16);
        v += __shfl_xor_sync(0xffffffffu, v, 4, 16);
        v += __shfl_xor_sync(0xffffffffu, v, 2, 16);
        v += __shfl_xor_sync(0xffffffffu, v, 1, 16);
        if (lane == 0) {
            float z   = __ldg(z_p + (size_t)t * (2 * DINNER));
            float sig = 1.f / (1.f + __expf(-z));
            y_p[(size_t)t * DINNER] = __float2bfloat16((v + x * Dd) * (z * sig));
        }
    }
}

// =======================================================================
extern "C" void kernel_launch(void* const* d_in, const int* in_sizes, int n_in,
                              void* d_out, int out_size) {
    const float* hs   = (const float*)d_in[0];
    const float* nw   = (const float*)d_in[1];
    const float* inw  = (const float*)d_in[2];
    const float* cw   = (const float*)d_in[3];
    const float* cb   = (const float*)d_in[4];
    const float* xpw  = (const float*)d_in[5];
    const float* dtw  = (const float*)d_in[6];
    const float* dtb  = (const float*)d_in[7];
    const float* alog = (const float*)d_in[8];
    const float* Dp   = (const float*)d_in[9];
    const float* ow   = (const float*)d_in[10];
    float* out = (float*)d_out;

    float *p_xz, *p_xc, *p_dbl, *p_dt;
    __nv_bfloat16 *p_hb, *p_xcb, *p_dblb, *p_yb, *p_inwb, *p_xpwb, *p_dtwb, *p_owb;
    cudaGetSymbolAddress((void**)&p_xz,   g_xz);
    cudaGetSymbolAddress((void**)&p_xc,   g_xc);
    cudaGetSymbolAddress((void**)&p_dbl,  g_dbl);
    cudaGetSymbolAddress((void**)&p_dt,   g_dt);
    cudaGetSymbolAddress((void**)&p_hb,   g_hb);
    cudaGetSymbolAddress((void**)&p_xcb,  g_xcb);
    cudaGetSymbolAddress((void**)&p_dblb, g_dblb);
    cudaGetSymbolAddress((void**)&p_yb,   g_yb);
    cudaGetSymbolAddress((void**)&p_inwb, g_inwb);
    cudaGetSymbolAddress((void**)&p_xpwb, g_xpwb);
    cudaGetSymbolAddress((void**)&p_dtwb, g_dtwb);
    cudaGetSymbolAddress((void**)&p_owb,  g_owb);

    // 0. weight conversions (independent of data path)
    k_f2bf<<<(2 * DINNER * DMODEL / 4 + 255) / 256, 256>>>(inw, p_inwb, 2 * DINNER * DMODEL);
    k_f2bf<<<(XPOUT * DINNER / 4 + 255) / 256, 256>>>(xpw, p_xpwb, XPOUT * DINNER);
    k_f2bf<<<(DINNER * DTRANK / 4 + 255) / 256, 256>>>(dtw, p_dtwb, DINNER * DTRANK);
    k_f2bf<<<(DMODEL * DINNER / 4 + 255) / 256, 256>>>(ow, p_owb, DMODEL * DINNER);

    // 1. RMSNorm -> bf16
    k_rmsnorm<<<NTOK, 256>>>(hs, nw);

    // 2. xz = h @ in_proj_w^T   (4096 x 4096, K=1024)
    k_bmma_nt<128, 128, 4, 2, 0, false><<<dim3(32, 32), 256>>>(
        p_hb, DMODEL, p_inwb, DMODEL, p_xz, 2 * DINNER, DMODEL, nullptr, nullptr);

    // 3. depthwise conv + SiLU -> fp32 + bf16
    k_conv_silu<<<(NTOK * DINNER) / 256, 256>>>(cw, cb);

    // 4. dbl = xc @ x_proj_w^T  (4096 x 96, K=2048) -> fp32 + bf16
    k_bmma_nt<64, 32, 2, 2, 0, true><<<dim3(3, 64), 128>>>(
        p_xcb, DINNER, p_xpwb, DINNER, p_dbl, XPOUT, DINNER, nullptr, p_dblb);

    // 5. dt = softplus(dt_r @ dt_proj_w^T + b)  (4096 x 2048, K=64, lda=96)
    k_bmma_nt<128, 128, 4, 2, 1, false><<<dim3(16, 32), 256>>>(
        p_dblb, XPOUT, p_dtwb, DTRANK, p_dt, DINNER, DTRANK, dtb, nullptr);

    // 6. selective scan + gating -> bf16 y
    k_scan<<<256, 256>>>(alog, Dp);

    // 7. out = y @ out_proj_w^T + residual  (4096 x 1024, K=2048)
    k_bmma_nt<128, 128, 4, 2, 2, false><<<dim3(8, 32), 256>>>(
        p_yb, DINNER, p_owb, DMODEL * 0 + DINNER, out, DMODEL, DINNER, hs, nullptr);
}

// round 5
// speedup vs baseline: 8.5244x; 3.9168x over previous
#include <cuda_runtime.h>
#include <cuda_bf16.h>
#include <math.h>
#include <stdint.h>

#define BSZ    2
#define SEQL   2048
#define DMODEL 1024
#define DINNER 2048
#define DSTATE 16
#define DTRANK 64
#define NTOK   (BSZ * SEQL)          // 4096
#define XPOUT  (DTRANK + 2 * DSTATE) // 96

// -------- scratch (static device globals; no runtime allocation) --------
__device__ float g_xz [(size_t)NTOK * 2 * DINNER];  // in_proj out (x | z) fp32
__device__ float g_xc [(size_t)NTOK * DINNER];      // conv+silu out fp32 (scan)
__device__ float g_dbl[(size_t)NTOK * XPOUT];       // x_proj out fp32 (scan B,C)
__device__ float g_dt [(size_t)NTOK * DINNER];      // softplus(dt) fp32 (scan)

__device__ __nv_bfloat16 g_hb  [(size_t)NTOK * DMODEL];   // rmsnorm out (A of in_proj)
__device__ __nv_bfloat16 g_xcb [(size_t)NTOK * DINNER];   // conv out (A of x_proj)
__device__ __nv_bfloat16 g_dblb[(size_t)NTOK * XPOUT];    // x_proj out (A of dt_proj)
__device__ __nv_bfloat16 g_yb  [(size_t)NTOK * DINNER];   // scan out (A of out_proj)
__device__ __nv_bfloat16 g_inwb[(size_t)2 * DINNER * DMODEL];
__device__ __nv_bfloat16 g_xpwb[(size_t)XPOUT * DINNER];
__device__ __nv_bfloat16 g_dtwb[(size_t)DINNER * DTRANK];
__device__ __nv_bfloat16 g_owb [(size_t)DMODEL * DINNER];

// =======================================================================
// helpers
// =======================================================================
__device__ __forceinline__ void cp_async16(void* smem_dst, const void* gmem_src) {
    uint32_t s = (uint32_t)__cvta_generic_to_shared(smem_dst);
    asm volatile("cp.async.cg.shared.global [%0], [%1], 16;\n" :: "r"(s), "l"(gmem_src));
}
__device__ __forceinline__ void cp_commit() {
    asm volatile("cp.async.commit_group;\n");
}
template<int N> __device__ __forceinline__ void cp_wait() {
    asm volatile("cp.async.wait_group %0;\n" :: "n"(N));
}
__device__ __forceinline__ void mma_bf16(float* c, const uint32_t* a, const uint32_t* b) {
    asm volatile(
        "mma.sync.aligned.m16n8k16.row.col.f32.bf16.bf16.f32 "
        "{%0,%1,%2,%3}, {%4,%5,%6,%7}, {%8,%9}, {%0,%1,%2,%3};"
        : "+f"(c[0]), "+f"(c[1]), "+f"(c[2]), "+f"(c[3])
        : "r"(a[0]), "r"(a[1]), "r"(a[2]), "r"(a[3]), "r"(b[0]), "r"(b[1]));
}

// fp32 -> bf16 conversion (weights), 4 per thread
__global__ void k_f2bf(const float* __restrict__ src, __nv_bfloat16* __restrict__ dst, int n) {
    int i = (blockIdx.x * blockDim.x + threadIdx.x) * 4;
    if (i + 3 < n) {
        float4 v = *(const float4*)(src + i);
        dst[i]     = __float2bfloat16(v.x);
        dst[i + 1] = __float2bfloat16(v.y);
        dst[i + 2] = __float2bfloat16(v.z);
        dst[i + 3] = __float2bfloat16(v.w);
    } else {
        for (int j = i; j < n; j++) dst[j] = __float2bfloat16(src[j]);
    }
}

// =======================================================================
// NT GEMM, bf16 tensor cores, cp.async double-buffered, BK=32.
// =======================================================================
template<int BM, int BN, int WARPS_M, int WARPS_N, int EPI, bool WB>
__global__ void __launch_bounds__(WARPS_M * WARPS_N * 32)
k_bmma_nt(const __nv_bfloat16* __restrict__ A, int lda,
          const __nv_bfloat16* __restrict__ B, int ldb,
          float* __restrict__ C, int ldc, int K,
          const float* __restrict__ extra, __nv_bfloat16* __restrict__ Cb)
{
    constexpr int BK = 32, LDS = 40;                 // halves; 20 words/row
    constexpr int THREADS = WARPS_M * WARPS_N * 32;
    constexpr int WM = BM / WARPS_M, WN = BN / WARPS_N;
    constexpr int MT = WM / 16, NT = WN / 8;
    constexpr int AITER = BM * BK / (THREADS * 8);
    constexpr int BITER = BN * BK / (THREADS * 8);

    __shared__ __nv_bfloat16 As[2][BM * LDS];
    __shared__ __nv_bfloat16 Bs[2][BN * LDS];

    int tid = threadIdx.x, lane = tid & 31, wid = tid >> 5;
    int wm = wid % WARPS_M, wn = wid / WARPS_M;
    int bm0 = blockIdx.y * BM, bn0 = blockIdx.x * BN;

    float acc[MT][NT][4];
    #pragma unroll
    for (int mt = 0; mt < MT; mt++)
        #pragma unroll
        for (int nt = 0; nt < NT; nt++)
            #pragma unroll
            for (int i = 0; i < 4; i++) acc[mt][nt][i] = 0.f;

    auto issue = [&](int kb, int buf) {
        #pragma unroll
        for (int i = 0; i < AITER; i++) {
            int e = tid + i * THREADS;
            int row = e >> 2, col = (e & 3) * 8;
            cp_async16(&As[buf][row * LDS + col],
                       A + (size_t)(bm0 + row) * lda + kb * BK + col);
        }
        #pragma unroll
        for (int i = 0; i < BITER; i++) {
            int e = tid + i * THREADS;
            int row = e >> 2, col = (e & 3) * 8;
            cp_async16(&Bs[buf][row * LDS + col],
                       B + (size_t)(bn0 + row) * ldb + kb * BK + col);
        }
        cp_commit();
    };

    int nkb = K / BK;
    issue(0, 0);

    for (int kb = 0; kb < nkb; kb++) {
        int buf = kb & 1;
        if (kb + 1 < nkb) {
            issue(kb + 1, buf ^ 1);
            cp_wait<1>();
        } else {
            cp_wait<0>();
        }
        __syncthreads();

        const uint32_t* Aw = (const uint32_t*)As[buf];
        const uint32_t* Bw = (const uint32_t*)Bs[buf];
        #pragma unroll
        for (int ks = 0; ks < 2; ks++) {
            int k0 = ks * 8 + (lane & 3);
            uint32_t af[MT][4], bfr[NT][2];
            #pragma unroll
            for (int mt = 0; mt < MT; mt++) {
                int r = wm * WM + mt * 16 + (lane >> 2);
                af[mt][0] = Aw[r * (LDS / 2) + k0];
                af[mt][1] = Aw[(r + 8) * (LDS / 2) + k0];
                af[mt][2] = Aw[r * (LDS / 2) + k0 + 4];
                af[mt][3] = Aw[(r + 8) * (LDS / 2) + k0 + 4];
            }
            #pragma unroll
            for (int nt = 0; nt < NT; nt++) {
                int n = wn * WN + nt * 8 + (lane >> 2);
                bfr[nt][0] = Bw[n * (LDS / 2) + k0];
                bfr[nt][1] = Bw[n * (LDS / 2) + k0 + 4];
            }
            #pragma unroll
            for (int mt = 0; mt < MT; mt++)
                #pragma unroll
                for (int nt = 0; nt < NT; nt++)
                    mma_bf16(acc[mt][nt], af[mt], bfr[nt]);
        }
        __syncthreads();
    }

    #pragma unroll
    for (int mt = 0; mt < MT; mt++) {
        int r0 = bm0 + wm * WM + mt * 16 + (lane >> 2);
        #pragma unroll
        for (int nt = 0; nt < NT; nt++) {
            int c0 = bn0 + wn * WN + nt * 8 + ((lane & 3) << 1);
            #pragma unroll
            for (int q = 0; q < 4; q++) {
                int m = r0 + (q >> 1) * 8;
                int n = c0 + (q & 1);
                float v = acc[mt][nt][q];
                if (EPI == 1) {
                    v += extra[n];
                    v = (v > 20.f) ? v : log1pf(expf(v));
                } else if (EPI == 2) {
                    v += extra[(size_t)m * ldc + n];
                }
                C[(size_t)m * ldc + n] = v;
                if (WB) Cb[(size_t)m * ldc + n] = __float2bfloat16(v);
            }
        }
    }
}

// =======================================================================
// RMSNorm -> bf16 output
// =======================================================================
__global__ void k_rmsnorm(const float* __restrict__ x, const float* __restrict__ w) {
    int row = blockIdx.x, tid = threadIdx.x;
    float4 v = ((const float4*)(x + (size_t)row * DMODEL))[tid];
    float ss = v.x * v.x + v.y * v.y + v.z * v.z + v.w * v.w;
    #pragma unroll
    for (int o = 16; o; o >>= 1) ss += __shfl_xor_sync(0xffffffffu, ss, o);
    __shared__ float sred[8];
    __shared__ float snorm;
    if ((tid & 31) == 0) sred[tid >> 5] = ss;
    __syncthreads();
    if (tid == 0) {
        float s = 0.f;
        #pragma unroll
        for (int i = 0; i < 8; i++) s += sred[i];
        snorm = rsqrtf(s * (1.0f / DMODEL) + 1e-5f);
    }
    __syncthreads();
    float r = snorm;
    float4 wv = ((const float4*)w)[tid];
    __nv_bfloat162 o0 = make_bfloat162(__float2bfloat16(v.x * r * wv.x),
                                       __float2bfloat16(v.y * r * wv.y));
    __nv_bfloat162 o1 = make_bfloat162(__float2bfloat16(v.z * r * wv.z),
                                       __float2bfloat16(v.w * r * wv.w));
    __nv_bfloat162* dst = (__nv_bfloat162*)(g_hb + (size_t)row * DMODEL) + tid * 2;
    dst[0] = o0; dst[1] = o1;
}

// =======================================================================
// Causal depthwise conv (width 4) + SiLU -> fp32 (scan) + bf16 (x_proj A)
// =======================================================================
__global__ void k_conv_silu(const float* __restrict__ cw, const float* __restrict__ cb) {
    size_t idx = (size_t)blockIdx.x * blockDim.x + threadIdx.x;
    if (idx >= (size_t)NTOK * DINNER) return;
    int d = (int)(idx & (DINNER - 1));
    int t = (int)((idx >> 11) & (SEQL - 1));
    int b = (int)(idx >> 22);
    const float* xp = g_xz + (size_t)b * SEQL * (2 * DINNER) + d;
    float acc = cb[d];
    #pragma unroll
    for (int j = 0; j < 4; j++) {
        int tt = t - 3 + j;
        if (tt >= 0)
            acc = fmaf(__ldg(cw + d * 4 + j), xp[(size_t)tt * (2 * DINNER)], acc);
    }
    float s = acc / (1.f + expf(-acc));
    g_xc[idx]  = s;
    g_xcb[idx] = __float2bfloat16(s);
}

// =======================================================================
// Selective scan v2: chunked smem staging, 16-lane shfl reduce.
// 512 threads = 32 channels (16 lanes each). grid = 128 (one wave).
// =======================================================================
__global__ __launch_bounds__(512) void k_scan2(const float* __restrict__ alog,
                                               const float* __restrict__ Dp) {
    constexpr int TCH = 32;
    __shared__ float xs [TCH][32];
    __shared__ float dts[TCH][32];
    __shared__ float zs [TCH][32];
    __shared__ float ys [TCH][32];
    __shared__ float Bs [TCH][16];
    __shared__ float Cs [TCH][16];

    int tid = threadIdx.x;
    int grp = tid >> 4;                 // channel within block (0..31)
    int l16 = tid & 15;                 // state index
    int b   = blockIdx.x >> 6;          // 64 blocks per batch
    int d0  = (blockIdx.x & 63) * 32;
    int d   = d0 + grp;

    float A2 = -expf(alog[d * DSTATE + l16]) * 1.44269504f;  // A * log2(e)
    float Dd = Dp[d];
    float h  = 0.f;

    const float* xc_base = g_xc  + (size_t)b * SEQL * DINNER + d0;
    const float* dt_base = g_dt  + (size_t)b * SEQL * DINNER + d0;
    const float* z_base  = g_xz  + (size_t)b * SEQL * (2 * DINNER) + DINNER + d0;
    const float* bl_base = g_dbl + (size_t)b * SEQL * XPOUT;
    __nv_bfloat16* y_base = g_yb + (size_t)b * SEQL * DINNER + d0;

    for (int t0 = 0; t0 < SEQL; t0 += TCH) {
        __syncthreads();   // protect ys/zs of previous chunk's store phase
        // ---- stage chunk (coalesced float4) ----
        if (tid < 256) {
            int r = tid >> 3, cq = (tid & 7) * 4;
            *(float4*)&xs[r][cq] =
                *(const float4*)(xc_base + (size_t)(t0 + r) * DINNER + cq);
            *(float4*)&zs[r][cq] =
                *(const float4*)(z_base + (size_t)(t0 + r) * (2 * DINNER) + cq);
        } else {
            int j = tid - 256;
            int r = j >> 3, f = j & 7;
            *(float4*)&dts[r][f * 4] =
                *(const float4*)(dt_base + (size_t)(t0 + r) * DINNER + f * 4);
            float4 v = *(const float4*)(bl_base + (size_t)(t0 + r) * XPOUT + DTRANK + f * 4);
            if (f < 4) *(float4*)&Bs[r][f * 4] = v;
            else       *(float4*)&Cs[r][(f - 4) * 4] = v;
        }
        __syncthreads();

        // ---- sequential recurrence over chunk ----
        #pragma unroll 4
        for (int tt = 0; tt < TCH; tt++) {
            float x  = xs[tt][grp];
            float dt = dts[tt][grp];
            float Bn = Bs[tt][l16];
            float Cn = Cs[tt][l16];
            float dA;
            asm("ex2.approx.f32 %0, %1;" : "=f"(dA) : "f"(dt * A2));
            h = fmaf(h, dA, dt * x * Bn);
            float v = h * Cn;
            v += __shfl_xor_sync(0xffffffffu, v, 8, 16);
            v += __shfl_xor_sync(0xffffffffu, v, 4, 16);
            v += __shfl_xor_sync(0xffffffffu, v, 2, 16);
            v += __shfl_xor_sync(0xffffffffu, v, 1, 16);
            if (l16 == 0) ys[tt][grp] = fmaf(x, Dd, v);
        }
        __syncthreads();

        // ---- gated bf16 store (coalesced) ----
        if (tid < 256) {
            int r = tid >> 3, cq = (tid & 7) * 4;
            float4 yv = *(float4*)&ys[r][cq];
            float4 zv = *(float4*)&zs[r][cq];
            __nv_bfloat16 o[4];
            float zg;
            zg = zv.x / (1.f + __expf(-zv.x)); o[0] = __float2bfloat16(yv.x * zg);
            zg = zv.y / (1.f + __expf(-zv.y)); o[1] = __float2bfloat16(yv.y * zg);
            zg = zv.z / (1.f + __expf(-zv.z)); o[2] = __float2bfloat16(yv.z * zg);
            zg = zv.w / (1.f + __expf(-zv.w)); o[3] = __float2bfloat16(yv.w * zg);
            *(uint2*)(y_base + (size_t)(t0 + r) * DINNER + cq) = *(uint2*)o;
        }
    }
}

// =======================================================================
extern "C" void kernel_launch(void* const* d_in, const int* in_sizes, int n_in,
                              void* d_out, int out_size) {
    const float* hs   = (const float*)d_in[0];
    const float* nw   = (const float*)d_in[1];
    const float* inw  = (const float*)d_in[2];
    const float* cw   = (const float*)d_in[3];
    const float* cb   = (const float*)d_in[4];
    const float* xpw  = (const float*)d_in[5];
    const float* dtw  = (const float*)d_in[6];
    const float* dtb  = (const float*)d_in[7];
    const float* alog = (const float*)d_in[8];
    const float* Dp   = (const float*)d_in[9];
    const float* ow   = (const float*)d_in[10];
    float* out = (float*)d_out;

    float *p_xz, *p_xc, *p_dbl, *p_dt;
    __nv_bfloat16 *p_hb, *p_xcb, *p_dblb, *p_yb, *p_inwb, *p_xpwb, *p_dtwb, *p_owb;
    cudaGetSymbolAddress((void**)&p_xz,   g_xz);
    cudaGetSymbolAddress((void**)&p_xc,   g_xc);
    cudaGetSymbolAddress((void**)&p_dbl,  g_dbl);
    cudaGetSymbolAddress((void**)&p_dt,   g_dt);
    cudaGetSymbolAddress((void**)&p_hb,   g_hb);
    cudaGetSymbolAddress((void**)&p_xcb,  g_xcb);
    cudaGetSymbolAddress((void**)&p_dblb, g_dblb);
    cudaGetSymbolAddress((void**)&p_yb,   g_yb);
    cudaGetSymbolAddress((void**)&p_inwb, g_inwb);
    cudaGetSymbolAddress((void**)&p_xpwb, g_xpwb);
    cudaGetSymbolAddress((void**)&p_dtwb, g_dtwb);
    cudaGetSymbolAddress((void**)&p_owb,  g_owb);

    // 0. weight conversions
    k_f2bf<<<(2 * DINNER * DMODEL / 4 + 255) / 256, 256>>>(inw, p_inwb, 2 * DINNER * DMODEL);
    k_f2bf<<<(XPOUT * DINNER / 4 + 255) / 256, 256>>>(xpw, p_xpwb, XPOUT * DINNER);
    k_f2bf<<<(DINNER * DTRANK / 4 + 255) / 256, 256>>>(dtw, p_dtwb, DINNER * DTRANK);
    k_f2bf<<<(DMODEL * DINNER / 4 + 255) / 256, 256>>>(ow, p_owb, DMODEL * DINNER);

    // 1. RMSNorm -> bf16
    k_rmsnorm<<<NTOK, 256>>>(hs, nw);

    // 2. xz = h @ in_proj_w^T   (4096 x 4096, K=1024)
    k_bmma_nt<128, 128, 4, 2, 0, false><<<dim3(32, 32), 256>>>(
        p_hb, DMODEL, p_inwb, DMODEL, p_xz, 2 * DINNER, DMODEL, nullptr, nullptr);

    // 3. depthwise conv + SiLU
    k_conv_silu<<<(NTOK * DINNER) / 256, 256>>>(cw, cb);

    // 4. dbl = xc @ x_proj_w^T  (4096 x 96, K=2048) -> fp32 + bf16
    k_bmma_nt<64, 32, 2, 2, 0, true><<<dim3(3, 64), 128>>>(
        p_xcb, DINNER, p_xpwb, DINNER, p_dbl, XPOUT, DINNER, nullptr, p_dblb);

    // 5. dt = softplus(dt_r @ dt_proj_w^T + b)  (4096 x 2048, K=64)
    k_bmma_nt<128, 128, 4, 2, 1, false><<<dim3(16, 32), 256>>>(
        p_dblb, XPOUT, p_dtwb, DTRANK, p_dt, DINNER, DTRANK, dtb, nullptr);

    // 6. selective scan + gating -> bf16 y
    k_scan2<<<128, 512>>>(alog, Dp);

    // 7. out = y @ out_proj_w^T + residual  (4096 x 1024, K=2048)
    k_bmma_nt<128, 128, 4, 2, 2, false><<<dim3(8, 32), 256>>>(
        p_yb, DINNER, p_owb, DINNER, out, DMODEL, DINNER, hs, nullptr);
}

// round 7
// speedup vs baseline: 8.9943x; 1.0551x over previous
#include <cuda_runtime.h>
#include <cuda_bf16.h>
#include <math.h>
#include <stdint.h>

#define BSZ    2
#define SEQL   2048
#define DMODEL 1024
#define DINNER 2048
#define DSTATE 16
#define DTRANK 64
#define NTOK   (BSZ * SEQL)          // 4096
#define XPOUT  (DTRANK + 2 * DSTATE) // 96

// -------- scratch (static device globals; no runtime allocation) --------
__device__ float g_xz [(size_t)NTOK * 2 * DINNER];  // in_proj out (x | z) fp32
__device__ float g_xc [(size_t)NTOK * DINNER];      // conv+silu out fp32 (scan)
__device__ float g_dbl[(size_t)NTOK * XPOUT];       // x_proj out fp32 (scan B,C)
__device__ float g_dt [(size_t)NTOK * DINNER];      // softplus(dt) fp32 (scan)

__device__ __nv_bfloat16 g_hb  [(size_t)NTOK * DMODEL];
__device__ __nv_bfloat16 g_xcb [(size_t)NTOK * DINNER];
__device__ __nv_bfloat16 g_dblb[(size_t)NTOK * XPOUT];
__device__ __nv_bfloat16 g_yb  [(size_t)NTOK * DINNER];
__device__ __nv_bfloat16 g_inwb[(size_t)2 * DINNER * DMODEL];
__device__ __nv_bfloat16 g_xpwb[(size_t)XPOUT * DINNER];
__device__ __nv_bfloat16 g_dtwb[(size_t)DINNER * DTRANK];
__device__ __nv_bfloat16 g_owb [(size_t)DMODEL * DINNER];

// =======================================================================
// helpers
// =======================================================================
__device__ __forceinline__ void cp16(void* smem_dst, const void* gmem_src) {
    uint32_t s = (uint32_t)__cvta_generic_to_shared(smem_dst);
    asm volatile("cp.async.cg.shared.global [%0], [%1], 16;" :: "r"(s), "l"(gmem_src));
}
__device__ __forceinline__ void cp_commit() { asm volatile("cp.async.commit_group;"); }
template<int N> __device__ __forceinline__ void cp_wait() {
    asm volatile("cp.async.wait_group %0;" :: "n"(N));
}
__device__ __forceinline__ void mma_bf16(float* c, const uint32_t* a, const uint32_t* b) {
    asm volatile(
        "mma.sync.aligned.m16n8k16.row.col.f32.bf16.bf16.f32 "
        "{%0,%1,%2,%3}, {%4,%5,%6,%7}, {%8,%9}, {%0,%1,%2,%3};"
        : "+f"(c[0]), "+f"(c[1]), "+f"(c[2]), "+f"(c[3])
        : "r"(a[0]), "r"(a[1]), "r"(a[2]), "r"(a[3]), "r"(b[0]), "r"(b[1]));
}

__global__ void k_f2bf(const float* __restrict__ src, __nv_bfloat16* __restrict__ dst, int n) {
    int i = (blockIdx.x * blockDim.x + threadIdx.x) * 4;
    if (i + 3 < n) {
        float4 v = *(const float4*)(src + i);
        dst[i]     = __float2bfloat16(v.x);
        dst[i + 1] = __float2bfloat16(v.y);
        dst[i + 2] = __float2bfloat16(v.z);
        dst[i + 3] = __float2bfloat16(v.w);
    } else {
        for (int j = i; j < n; j++) dst[j] = __float2bfloat16(src[j]);
    }
}

// =======================================================================
// NT GEMM, bf16 mma.sync, multi-stage cp.async pipeline, BK=32.
// C[M,N] = A[M,K]·B[N,K]^T.  All dims divide the tile config.
// EPI: 0=none, 1=softplus(v+extra[n]), 2=v+extra[m*ldc+n]
// WB: also write bf16 copy to Cb
// =======================================================================
template<int BM, int BN, int WARPS_M, int WARPS_N, int STAGES, int EPI, bool WB>
__global__ void __launch_bounds__(WARPS_M * WARPS_N * 32)
k_bmma_nt(const __nv_bfloat16* __restrict__ A, int lda,
          const __nv_bfloat16* __restrict__ B, int ldb,
          float* __restrict__ C, int ldc, int K,
          const float* __restrict__ extra, __nv_bfloat16* __restrict__ Cb)
{
    constexpr int BK = 32, LDS = 40;                 // halves; 20 words/row
    constexpr int THREADS = WARPS_M * WARPS_N * 32;
    constexpr int WM = BM / WARPS_M, WN = BN / WARPS_N;
    constexpr int MT = WM / 16, NT = WN / 8;
    constexpr int AITER = BM * BK / (THREADS * 8);
    constexpr int BITER = BN * BK / (THREADS * 8);

    extern __shared__ __nv_bfloat16 smd[];
    __nv_bfloat16* As = smd;                          // [STAGES][BM*LDS]
    __nv_bfloat16* Bs = smd + (size_t)STAGES * BM * LDS;

    int tid = threadIdx.x, lane = tid & 31, wid = tid >> 5;
    int wm = wid % WARPS_M, wn = wid / WARPS_M;
    int bm0 = blockIdx.y * BM, bn0 = blockIdx.x * BN;

    float acc[MT][NT][4];
    #pragma unroll
    for (int mt = 0; mt < MT; mt++)
        #pragma unroll
        for (int nt = 0; nt < NT; nt++)
            #pragma unroll
            for (int i = 0; i < 4; i++) acc[mt][nt][i] = 0.f;

    auto issue = [&](int kb, int buf) {
        __nv_bfloat16* Ab = As + (size_t)buf * BM * LDS;
        __nv_bfloat16* Bb = Bs + (size_t)buf * BN * LDS;
        #pragma unroll
        for (int i = 0; i < AITER; i++) {
            int e = tid + i * THREADS;
            int row = e >> 2, col = (e & 3) * 8;
            cp16(&Ab[row * LDS + col],
                 A + (size_t)(bm0 + row) * lda + kb * BK + col);
        }
        #pragma unroll
        for (int i = 0; i < BITER; i++) {
            int e = tid + i * THREADS;
            int row = e >> 2, col = (e & 3) * 8;
            cp16(&Bb[row * LDS + col],
                 B + (size_t)(bn0 + row) * ldb + kb * BK + col);
        }
        cp_commit();
    };

    int nkb = K / BK;
    #pragma unroll
    for (int s = 0; s < STAGES - 1; s++) {
        if (s < nkb) issue(s, s); else cp_commit();
    }

    for (int kb = 0; kb < nkb; kb++) {
        int buf = kb % STAGES;
        cp_wait<STAGES - 2>();
        __syncthreads();

        const uint32_t* Aw = (const uint32_t*)(As + (size_t)buf * BM * LDS);
        const uint32_t* Bw = (const uint32_t*)(Bs + (size_t)buf * BN * LDS);
        #pragma unroll
        for (int ks = 0; ks < 2; ks++) {
            int k0 = ks * 8 + (lane & 3);
            uint32_t af[MT][4], bfr[NT][2];
            #pragma unroll
            for (int mt = 0; mt < MT; mt++) {
                int r = wm * WM + mt * 16 + (lane >> 2);
                af[mt][0] = Aw[r * (LDS / 2) + k0];
                af[mt][1] = Aw[(r + 8) * (LDS / 2) + k0];
                af[mt][2] = Aw[r * (LDS / 2) + k0 + 4];
                af[mt][3] = Aw[(r + 8) * (LDS / 2) + k0 + 4];
            }
            #pragma unroll
            for (int nt = 0; nt < NT; nt++) {
                int n = wn * WN + nt * 8 + (lane >> 2);
                bfr[nt][0] = Bw[n * (LDS / 2) + k0];
                bfr[nt][1] = Bw[n * (LDS / 2) + k0 + 4];
            }
            #pragma unroll
            for (int mt = 0; mt < MT; mt++)
                #pragma unroll
                for (int nt = 0; nt < NT; nt++)
                    mma_bf16(acc[mt][nt], af[mt], bfr[nt]);
        }

        int nxt = kb + STAGES - 1;
        if (nxt < nkb) issue(nxt, nxt % STAGES);
        else cp_commit();
    }

    // epilogue
    #pragma unroll
    for (int mt = 0; mt < MT; mt++) {
        int r0 = bm0 + wm * WM + mt * 16 + (lane >> 2);
        #pragma unroll
        for (int nt = 0; nt < NT; nt++) {
            int c0 = bn0 + wn * WN + nt * 8 + ((lane & 3) << 1);
            #pragma unroll
            for (int q = 0; q < 4; q++) {
                int m = r0 + (q >> 1) * 8;
                int n = c0 + (q & 1);
                float v = acc[mt][nt][q];
                if (EPI == 1) {
                    v += extra[n];
                    v = (v > 20.f) ? v : log1pf(expf(v));
                } else if (EPI == 2) {
                    v += extra[(size_t)m * ldc + n];
                }
                C[(size_t)m * ldc + n] = v;
                if (WB) Cb[(size_t)m * ldc + n] = __float2bfloat16(v);
            }
        }
    }
}

// =======================================================================
// RMSNorm -> bf16 output
// =======================================================================
__global__ void k_rmsnorm(const float* __restrict__ x, const float* __restrict__ w) {
    int row = blockIdx.x, tid = threadIdx.x;
    float4 v = ((const float4*)(x + (size_t)row * DMODEL))[tid];
    float ss = v.x * v.x + v.y * v.y + v.z * v.z + v.w * v.w;
    #pragma unroll
    for (int o = 16; o; o >>= 1) ss += __shfl_xor_sync(0xffffffffu, ss, o);
    __shared__ float sred[8];
    __shared__ float snorm;
    if ((tid & 31) == 0) sred[tid >> 5] = ss;
    __syncthreads();
    if (tid == 0) {
        float s = 0.f;
        #pragma unroll
        for (int i = 0; i < 8; i++) s += sred[i];
        snorm = rsqrtf(s * (1.0f / DMODEL) + 1e-5f);
    }
    __syncthreads();
    float r = snorm;
    float4 wv = ((const float4*)w)[tid];
    __nv_bfloat162 o0 = make_bfloat162(__float2bfloat16(v.x * r * wv.x),
                                       __float2bfloat16(v.y * r * wv.y));
    __nv_bfloat162 o1 = make_bfloat162(__float2bfloat16(v.z * r * wv.z),
                                       __float2bfloat16(v.w * r * wv.w));
    __nv_bfloat162* dst = (__nv_bfloat162*)(g_hb + (size_t)row * DMODEL) + tid * 2;
    dst[0] = o0; dst[1] = o1;
}

// =======================================================================
// Causal depthwise conv (width 4) + SiLU -> fp32 (scan) + bf16 (x_proj A)
// =======================================================================
__global__ void k_conv_silu(const float* __restrict__ cw, const float* __restrict__ cb) {
    size_t idx = (size_t)blockIdx.x * blockDim.x + threadIdx.x;
    if (idx >= (size_t)NTOK * DINNER) return;
    int d = (int)(idx & (DINNER - 1));
    int t = (int)((idx >> 11) & (SEQL - 1));
    int b = (int)(idx >> 22);
    const float* xp = g_xz + (size_t)b * SEQL * (2 * DINNER) + d;
    float acc = cb[d];
    #pragma unroll
    for (int j = 0; j < 4; j++) {
        int tt = t - 3 + j;
        if (tt >= 0)
            acc = fmaf(__ldg(cw + d * 4 + j), xp[(size_t)tt * (2 * DINNER)], acc);
    }
    float s = acc / (1.f + expf(-acc));
    g_xc[idx]  = s;
    g_xcb[idx] = __float2bfloat16(s);
}

// =======================================================================
// Selective scan v2 (round-5 version, unchanged — it delivered)
// =======================================================================
__global__ __launch_bounds__(512) void k_scan2(const float* __restrict__ alog,
                                               const float* __restrict__ Dp) {
    constexpr int TCH = 32;
    __shared__ float xs [TCH][32];
    __shared__ float dts[TCH][32];
    __shared__ float zs [TCH][32];
    __shared__ float ys [TCH][32];
    __shared__ float Bs [TCH][16];
    __shared__ float Cs [TCH][16];

    int tid = threadIdx.x;
    int grp = tid >> 4;
    int l16 = tid & 15;
    int b   = blockIdx.x >> 6;
    int d0  = (blockIdx.x & 63) * 32;
    int d   = d0 + grp;

    float A2 = -expf(alog[d * DSTATE + l16]) * 1.44269504f;
    float Dd = Dp[d];
    float h  = 0.f;

    const float* xc_base = g_xc  + (size_t)b * SEQL * DINNER + d0;
    const float* dt_base = g_dt  + (size_t)b * SEQL * DINNER + d0;
    const float* z_base  = g_xz  + (size_t)b * SEQL * (2 * DINNER) + DINNER + d0;
    const float* bl_base = g_dbl + (size_t)b * SEQL * XPOUT;
    __nv_bfloat16* y_base = g_yb + (size_t)b * SEQL * DINNER + d0;

    for (int t0 = 0; t0 < SEQL; t0 += TCH) {
        __syncthreads();
        if (tid < 256) {
            int r = tid >> 3, cq = (tid & 7) * 4;
            *(float4*)&xs[r][cq] =
                *(const float4*)(xc_base + (size_t)(t0 + r) * DINNER + cq);
            *(float4*)&zs[r][cq] =
                *(const float4*)(z_base + (size_t)(t0 + r) * (2 * DINNER) + cq);
        } else {
            int j = tid - 256;
            int r = j >> 3, f = j & 7;
            *(float4*)&dts[r][f * 4] =
                *(const float4*)(dt_base + (size_t)(t0 + r) * DINNER + f * 4);
            float4 v = *(const float4*)(bl_base + (size_t)(t0 + r) * XPOUT + DTRANK + f * 4);
            if (f < 4) *(float4*)&Bs[r][f * 4] = v;
            else       *(float4*)&Cs[r][(f - 4) * 4] = v;
        }
        __syncthreads();

        #pragma unroll 4
        for (int tt = 0; tt < TCH; tt++) {
            float x  = xs[tt][grp];
            float dt = dts[tt][grp];
            float Bn = Bs[tt][l16];
            float Cn = Cs[tt][l16];
            float dA;
            asm("ex2.approx.f32 %0, %1;" : "=f"(dA) : "f"(dt * A2));
            h = fmaf(h, dA, dt * x * Bn);
            float v = h * Cn;
            v += __shfl_xor_sync(0xffffffffu, v, 8, 16);
            v += __shfl_xor_sync(0xffffffffu, v, 4, 16);
            v += __shfl_xor_sync(0xffffffffu, v, 2, 16);
            v += __shfl_xor_sync(0xffffffffu, v, 1, 16);
            if (l16 == 0) ys[tt][grp] = fmaf(x, Dd, v);
        }
        __syncthreads();

        if (tid < 256) {
            int r = tid >> 3, cq = (tid & 7) * 4;
            float4 yv = *(float4*)&ys[r][cq];
            float4 zv = *(float4*)&zs[r][cq];
            __nv_bfloat16 o[4];
            float zg;
            zg = zv.x / (1.f + __expf(-zv.x)); o[0] = __float2bfloat16(yv.x * zg);
            zg = zv.y / (1.f + __expf(-zv.y)); o[1] = __float2bfloat16(yv.y * zg);
            zg = zv.z / (1.f + __expf(-zv.z)); o[2] = __float2bfloat16(yv.z * zg);
            zg = zv.w / (1.f + __expf(-zv.w)); o[3] = __float2bfloat16(yv.w * zg);
            *(uint2*)(y_base + (size_t)(t0 + r) * DINNER + cq) = *(uint2*)o;
        }
    }
}

// =======================================================================
extern "C" void kernel_launch(void* const* d_in, const int* in_sizes, int n_in,
                              void* d_out, int out_size) {
    const float* hs   = (const float*)d_in[0];
    const float* nw   = (const float*)d_in[1];
    const float* inw  = (const float*)d_in[2];
    const float* cw   = (const float*)d_in[3];
    const float* cb   = (const float*)d_in[4];
    const float* xpw  = (const float*)d_in[5];
    const float* dtw  = (const float*)d_in[6];
    const float* dtb  = (const float*)d_in[7];
    const float* alog = (const float*)d_in[8];
    const float* Dp   = (const float*)d_in[9];
    const float* ow   = (const float*)d_in[10];
    float* out = (float*)d_out;

    float *p_xz, *p_xc, *p_dbl, *p_dt;
    __nv_bfloat16 *p_hb, *p_xcb, *p_dblb, *p_yb, *p_inwb, *p_xpwb, *p_dtwb, *p_owb;
    cudaGetSymbolAddress((void**)&p_xz,   g_xz);
    cudaGetSymbolAddress((void**)&p_xc,   g_xc);
    cudaGetSymbolAddress((void**)&p_dbl,  g_dbl);
    cudaGetSymbolAddress((void**)&p_dt,   g_dt);
    cudaGetSymbolAddress((void**)&p_hb,   g_hb);
    cudaGetSymbolAddress((void**)&p_xcb,  g_xcb);
    cudaGetSymbolAddress((void**)&p_dblb, g_dblb);
    cudaGetSymbolAddress((void**)&p_yb,   g_yb);
    cudaGetSymbolAddress((void**)&p_inwb, g_inwb);
    cudaGetSymbolAddress((void**)&p_xpwb, g_xpwb);
    cudaGetSymbolAddress((void**)&p_dtwb, g_dtwb);
    cudaGetSymbolAddress((void**)&p_owb,  g_owb);

    // dynamic smem: STAGES * (BM + BN) * 40 halves
    const int SM_BIG = 4 * (128 + 128) * 40 * 2;   // 81920 B
    const int SM_XP  = 4 * (64 + 32) * 40 * 2;     // 30720 B
    cudaFuncSetAttribute((const void*)k_bmma_nt<128, 128, 4, 2, 4, 0, false>,
                         cudaFuncAttributeMaxDynamicSharedMemorySize, SM_BIG);
    cudaFuncSetAttribute((const void*)k_bmma_nt<128, 128, 4, 2, 4, 1, false>,
                         cudaFuncAttributeMaxDynamicSharedMemorySize, SM_BIG);
    cudaFuncSetAttribute((const void*)k_bmma_nt<128, 128, 4, 2, 4, 2, false>,
                         cudaFuncAttributeMaxDynamicSharedMemorySize, SM_BIG);
    cudaFuncSetAttribute((const void*)k_bmma_nt<64, 32, 2, 2, 4, 0, true>,
                         cudaFuncAttributeMaxDynamicSharedMemorySize, SM_XP);

    // 0. weight conversions
    k_f2bf<<<(2 * DINNER * DMODEL / 4 + 255) / 256, 256>>>(inw, p_inwb, 2 * DINNER * DMODEL);
    k_f2bf<<<(XPOUT * DINNER / 4 + 255) / 256, 256>>>(xpw, p_xpwb, XPOUT * DINNER);
    k_f2bf<<<(DINNER * DTRANK / 4 + 255) / 256, 256>>>(dtw, p_dtwb, DINNER * DTRANK);
    k_f2bf<<<(DMODEL * DINNER / 4 + 255) / 256, 256>>>(ow, p_owb, DMODEL * DINNER);

    // 1. RMSNorm -> bf16
    k_rmsnorm<<<NTOK, 256>>>(hs, nw);

    // 2. xz = h @ in_proj_w^T   (4096 x 4096, K=1024)
    k_bmma_nt<128, 128, 4, 2, 4, 0, false><<<dim3(32, 32), 256, SM_BIG>>>(
        p_hb, DMODEL, p_inwb, DMODEL, p_xz, 2 * DINNER, DMODEL, nullptr, nullptr);

    // 3. depthwise conv + SiLU
    k_conv_silu<<<(NTOK * DINNER) / 256, 256>>>(cw, cb);

    // 4. dbl = xc @ x_proj_w^T  (4096 x 96, K=2048) -> fp32 + bf16
    k_bmma_nt<64, 32, 2, 2, 4, 0, true><<<dim3(3, 64), 128, SM_XP>>>(
        p_xcb, DINNER, p_xpwb, DINNER, p_dbl, XPOUT, DINNER, nullptr, p_dblb);

    // 5. dt = softplus(dt_r @ dt_proj_w^T + b)  (4096 x 2048, K=64)
    k_bmma_nt<128, 128, 4, 2, 4, 1, false><<<dim3(16, 32), 256, SM_BIG>>>(
        p_dblb, XPOUT, p_dtwb, DTRANK, p_dt, DINNER, DTRANK, dtb, nullptr);

    // 6. selective scan + gating -> bf16 y
    k_scan2<<<128, 512>>>(alog, Dp);

    // 7. out = y @ out_proj_w^T + residual  (4096 x 1024, K=2048)
    k_bmma_nt<128, 128, 4, 2, 4, 2, false><<<dim3(8, 32), 256, SM_BIG>>>(
        p_yb, DINNER, p_owb, DINNER, out, DMODEL, DINNER, hs, nullptr);
}

// round 8
// speedup vs baseline: 9.3857x; 1.0435x over previous
#include <cuda_runtime.h>
#include <cuda_bf16.h>
#include <math.h>
#include <stdint.h>

#define BSZ    2
#define SEQL   2048
#define DMODEL 1024
#define DINNER 2048
#define DSTATE 16
#define DTRANK 64
#define NTOK   (BSZ * SEQL)          // 4096
#define XPOUT  (DTRANK + 2 * DSTATE) // 96

// -------- scratch (static device globals; no runtime allocation) --------
__device__ float g_xz [(size_t)NTOK * 2 * DINNER];  // in_proj out (x | z) fp32
__device__ float g_xc [(size_t)NTOK * DINNER];      // conv+silu out fp32 (scan)
__device__ float g_dbl[(size_t)NTOK * XPOUT];       // x_proj out fp32 (scan B,C)
__device__ float g_dt [(size_t)NTOK * DINNER];      // softplus(dt) fp32 (scan)

__device__ __nv_bfloat16 g_hb  [(size_t)NTOK * DMODEL];
__device__ __nv_bfloat16 g_xcb [(size_t)NTOK * DINNER];
__device__ __nv_bfloat16 g_dblb[(size_t)NTOK * XPOUT];
__device__ __nv_bfloat16 g_yb  [(size_t)NTOK * DINNER];
__device__ __nv_bfloat16 g_inwb[(size_t)2 * DINNER * DMODEL];
__device__ __nv_bfloat16 g_xpwb[(size_t)XPOUT * DINNER];
__device__ __nv_bfloat16 g_dtwb[(size_t)DINNER * DTRANK];
__device__ __nv_bfloat16 g_owb [(size_t)DMODEL * DINNER];

// =======================================================================
// helpers
// =======================================================================
__device__ __forceinline__ void cp16(void* smem_dst, const void* gmem_src) {
    uint32_t s = (uint32_t)__cvta_generic_to_shared(smem_dst);
    asm volatile("cp.async.cg.shared.global [%0], [%1], 16;" :: "r"(s), "l"(gmem_src));
}
__device__ __forceinline__ void cp_commit() { asm volatile("cp.async.commit_group;"); }
template<int N> __device__ __forceinline__ void cp_wait() {
    asm volatile("cp.async.wait_group %0;" :: "n"(N));
}
__device__ __forceinline__ void mma_bf16(float* c, const uint32_t* a, const uint32_t* b) {
    asm volatile(
        "mma.sync.aligned.m16n8k16.row.col.f32.bf16.bf16.f32 "
        "{%0,%1,%2,%3}, {%4,%5,%6,%7}, {%8,%9}, {%0,%1,%2,%3};"
        : "+f"(c[0]), "+f"(c[1]), "+f"(c[2]), "+f"(c[3])
        : "r"(a[0]), "r"(a[1]), "r"(a[2]), "r"(a[3]), "r"(b[0]), "r"(b[1]));
}
__device__ __forceinline__ void ldsm4(uint32_t* r, uint32_t addr) {
    asm volatile("ldmatrix.sync.aligned.m8n8.x4.shared.b16 {%0,%1,%2,%3}, [%4];"
        : "=r"(r[0]), "=r"(r[1]), "=r"(r[2]), "=r"(r[3]) : "r"(addr));
}

__global__ void k_f2bf(const float* __restrict__ src, __nv_bfloat16* __restrict__ dst, int n) {
    int i = (blockIdx.x * blockDim.x + threadIdx.x) * 4;
    if (i + 3 < n) {
        float4 v = *(const float4*)(src + i);
        dst[i]     = __float2bfloat16(v.x);
        dst[i + 1] = __float2bfloat16(v.y);
        dst[i + 2] = __float2bfloat16(v.z);
        dst[i + 3] = __float2bfloat16(v.w);
    } else {
        for (int j = i; j < n; j++) dst[j] = __float2bfloat16(src[j]);
    }
}

// =======================================================================
// NT GEMM, bf16 mma.sync + ldmatrix, multi-stage cp.async pipeline, BK=32.
// C[M,N] = A[M,K]·B[N,K]^T.  All dims divide the tile config.
// EPI: 0=none, 1=softplus(v+extra[n]), 2=v+extra[m*ldc+n]
// WB: also write bf16 copy to Cb
// =======================================================================
template<int BM, int BN, int WARPS_M, int WARPS_N, int STAGES, int EPI, bool WB>
__global__ void __launch_bounds__(WARPS_M * WARPS_N * 32)
k_bmma_nt(const __nv_bfloat16* __restrict__ A, int lda,
          const __nv_bfloat16* __restrict__ B, int ldb,
          float* __restrict__ C, int ldc, int K,
          const float* __restrict__ extra, __nv_bfloat16* __restrict__ Cb)
{
    constexpr int BK = 32, LDS = 40;                 // halves; 20 words/row
    constexpr int THREADS = WARPS_M * WARPS_N * 32;
    constexpr int WM = BM / WARPS_M, WN = BN / WARPS_N;
    constexpr int MT = WM / 16, NT = WN / 8;
    constexpr int AITER = BM * BK / (THREADS * 8);
    constexpr int BITER = BN * BK / (THREADS * 8);

    extern __shared__ __nv_bfloat16 smd[];
    __nv_bfloat16* As = smd;                          // [STAGES][BM*LDS]
    __nv_bfloat16* Bs = smd + (size_t)STAGES * BM * LDS;
    uint32_t As_u = (uint32_t)__cvta_generic_to_shared(As);
    uint32_t Bs_u = (uint32_t)__cvta_generic_to_shared(Bs);

    int tid = threadIdx.x, lane = tid & 31, wid = tid >> 5;
    int wm = wid % WARPS_M, wn = wid / WARPS_M;
    int bm0 = blockIdx.y * BM, bn0 = blockIdx.x * BN;

    float acc[MT][NT][4];
    #pragma unroll
    for (int mt = 0; mt < MT; mt++)
        #pragma unroll
        for (int nt = 0; nt < NT; nt++)
            #pragma unroll
            for (int i = 0; i < 4; i++) acc[mt][nt][i] = 0.f;

    auto issue = [&](int kb, int buf) {
        __nv_bfloat16* Ab = As + (size_t)buf * BM * LDS;
        __nv_bfloat16* Bb = Bs + (size_t)buf * BN * LDS;
        #pragma unroll
        for (int i = 0; i < AITER; i++) {
            int e = tid + i * THREADS;
            int row = e >> 2, col = (e & 3) * 8;
            cp16(&Ab[row * LDS + col],
                 A + (size_t)(bm0 + row) * lda + kb * BK + col);
        }
        #pragma unroll
        for (int i = 0; i < BITER; i++) {
            int e = tid + i * THREADS;
            int row = e >> 2, col = (e & 3) * 8;
            cp16(&Bb[row * LDS + col],
                 B + (size_t)(bn0 + row) * ldb + kb * BK + col);
        }
        cp_commit();
    };

    int nkb = K / BK;
    #pragma unroll
    for (int s = 0; s < STAGES - 1; s++) {
        if (s < nkb) issue(s, s); else cp_commit();
    }

    // per-thread ldmatrix lane geometry (constant across iters)
    const int a_row_l = (lane & 15);            // row within 16-row tile
    const int a_colh  = (lane >> 4) * 8;        // 0 or 8 (k-half)
    const int b_row_l = (lane & 7);
    const int b_q     = lane >> 3;              // 0..3
    const int b_rowh  = (b_q >> 1) * 8;         // 0 or 8 (n-half of pair)
    const int b_colh  = (b_q & 1) * 8;          // 0 or 8 (k-half)

    for (int kb = 0; kb < nkb; kb++) {
        int buf = kb % STAGES;
        cp_wait<STAGES - 2>();
        __syncthreads();

        uint32_t Au = As_u + (uint32_t)buf * BM * LDS * 2;
        uint32_t Bu = Bs_u + (uint32_t)buf * BN * LDS * 2;
        #pragma unroll
        for (int ks = 0; ks < 2; ks++) {
            uint32_t af[MT][4], bfr[NT][2];
            #pragma unroll
            for (int mt = 0; mt < MT; mt++) {
                int r = wm * WM + mt * 16 + a_row_l;
                ldsm4(af[mt], Au + (uint32_t)(r * LDS + ks * 16 + a_colh) * 2);
            }
            #pragma unroll
            for (int p = 0; p < NT / 2; p++) {
                int n = wn * WN + p * 16 + b_rowh + b_row_l;
                uint32_t bq[4];
                ldsm4(bq, Bu + (uint32_t)(n * LDS + ks * 16 + b_colh) * 2);
                bfr[2 * p][0]     = bq[0];
                bfr[2 * p][1]     = bq[1];
                bfr[2 * p + 1][0] = bq[2];
                bfr[2 * p + 1][1] = bq[3];
            }
            #pragma unroll
            for (int mt = 0; mt < MT; mt++)
                #pragma unroll
                for (int nt = 0; nt < NT; nt++)
                    mma_bf16(acc[mt][nt], af[mt], bfr[nt]);
        }

        int nxt = kb + STAGES - 1;
        if (nxt < nkb) issue(nxt, nxt % STAGES);
        else cp_commit();
    }

    // epilogue
    #pragma unroll
    for (int mt = 0; mt < MT; mt++) {
        int r0 = bm0 + wm * WM + mt * 16 + (lane >> 2);
        #pragma unroll
        for (int nt = 0; nt < NT; nt++) {
            int c0 = bn0 + wn * WN + nt * 8 + ((lane & 3) << 1);
            #pragma unroll
            for (int q = 0; q < 4; q++) {
                int m = r0 + (q >> 1) * 8;
                int n = c0 + (q & 1);
                float v = acc[mt][nt][q];
                if (EPI == 1) {
                    v += extra[n];
                    v = (v > 20.f) ? v : log1pf(expf(v));
                } else if (EPI == 2) {
                    v += extra[(size_t)m * ldc + n];
                }
                C[(size_t)m * ldc + n] = v;
                if (WB) Cb[(size_t)m * ldc + n] = __float2bfloat16(v);
            }
        }
    }
}

// =======================================================================
// RMSNorm -> bf16 output
// =======================================================================
__global__ void k_rmsnorm(const float* __restrict__ x, const float* __restrict__ w) {
    int row = blockIdx.x, tid = threadIdx.x;
    float4 v = ((const float4*)(x + (size_t)row * DMODEL))[tid];
    float ss = v.x * v.x + v.y * v.y + v.z * v.z + v.w * v.w;
    #pragma unroll
    for (int o = 16; o; o >>= 1) ss += __shfl_xor_sync(0xffffffffu, ss, o);
    __shared__ float sred[8];
    __shared__ float snorm;
    if ((tid & 31) == 0) sred[tid >> 5] = ss;
    __syncthreads();
    if (tid == 0) {
        float s = 0.f;
        #pragma unroll
        for (int i = 0; i < 8; i++) s += sred[i];
        snorm = rsqrtf(s * (1.0f / DMODEL) + 1e-5f);
    }
    __syncthreads();
    float r = snorm;
    float4 wv = ((const float4*)w)[tid];
    __nv_bfloat162 o0 = make_bfloat162(__float2bfloat16(v.x * r * wv.x),
                                       __float2bfloat16(v.y * r * wv.y));
    __nv_bfloat162 o1 = make_bfloat162(__float2bfloat16(v.z * r * wv.z),
                                       __float2bfloat16(v.w * r * wv.w));
    __nv_bfloat162* dst = (__nv_bfloat162*)(g_hb + (size_t)row * DMODEL) + tid * 2;
    dst[0] = o0; dst[1] = o1;
}

// =======================================================================
// Causal depthwise conv (width 4) + SiLU -> fp32 (scan) + bf16 (x_proj A)
// =======================================================================
__global__ void k_conv_silu(const float* __restrict__ cw, const float* __restrict__ cb) {
    size_t idx = (size_t)blockIdx.x * blockDim.x + threadIdx.x;
    if (idx >= (size_t)NTOK * DINNER) return;
    int d = (int)(idx & (DINNER - 1));
    int t = (int)((idx >> 11) & (SEQL - 1));
    int b = (int)(idx >> 22);
    const float* xp = g_xz + (size_t)b * SEQL * (2 * DINNER) + d;
    float acc = cb[d];
    #pragma unroll
    for (int j = 0; j < 4; j++) {
        int tt = t - 3 + j;
        if (tt >= 0)
            acc = fmaf(__ldg(cw + d * 4 + j), xp[(size_t)tt * (2 * DINNER)], acc);
    }
    float s = acc / (1.f + expf(-acc));
    g_xc[idx]  = s;
    g_xcb[idx] = __float2bfloat16(s);
}

// =======================================================================
// Selective scan v2 (round-5 version, unchanged — it delivered)
// =======================================================================
__global__ __launch_bounds__(512) void k_scan2(const float* __restrict__ alog,
                                               const float* __restrict__ Dp) {
    constexpr int TCH = 32;
    __shared__ float xs [TCH][32];
    __shared__ float dts[TCH][32];
    __shared__ float zs [TCH][32];
    __shared__ float ys [TCH][32];
    __shared__ float Bs [TCH][16];
    __shared__ float Cs [TCH][16];

    int tid = threadIdx.x;
    int grp = tid >> 4;
    int l16 = tid & 15;
    int b   = blockIdx.x >> 6;
    int d0  = (blockIdx.x & 63) * 32;
    int d   = d0 + grp;

    float A2 = -expf(alog[d * DSTATE + l16]) * 1.44269504f;
    float Dd = Dp[d];
    float h  = 0.f;

    const float* xc_base = g_xc  + (size_t)b * SEQL * DINNER + d0;
    const float* dt_base = g_dt  + (size_t)b * SEQL * DINNER + d0;
    const float* z_base  = g_xz  + (size_t)b * SEQL * (2 * DINNER) + DINNER + d0;
    const float* bl_base = g_dbl + (size_t)b * SEQL * XPOUT;
    __nv_bfloat16* y_base = g_yb + (size_t)b * SEQL * DINNER + d0;

    for (int t0 = 0; t0 < SEQL; t0 += TCH) {
        __syncthreads();
        if (tid < 256) {
            int r = tid >> 3, cq = (tid & 7) * 4;
            *(float4*)&xs[r][cq] =
                *(const float4*)(xc_base + (size_t)(t0 + r) * DINNER + cq);
            *(float4*)&zs[r][cq] =
                *(const float4*)(z_base + (size_t)(t0 + r) * (2 * DINNER) + cq);
        } else {
            int j = tid - 256;
            int r = j >> 3, f = j & 7;
            *(float4*)&dts[r][f * 4] =
                *(const float4*)(dt_base + (size_t)(t0 + r) * DINNER + f * 4);
            float4 v = *(const float4*)(bl_base + (size_t)(t0 + r) * XPOUT + DTRANK + f * 4);
            if (f < 4) *(float4*)&Bs[r][f * 4] = v;
            else       *(float4*)&Cs[r][(f - 4) * 4] = v;
        }
        __syncthreads();

        #pragma unroll 4
        for (int tt = 0; tt < TCH; tt++) {
            float x  = xs[tt][grp];
            float dt = dts[tt][grp];
            float Bn = Bs[tt][l16];
            float Cn = Cs[tt][l16];
            float dA;
            asm("ex2.approx.f32 %0, %1;" : "=f"(dA) : "f"(dt * A2));
            h = fmaf(h, dA, dt * x * Bn);
            float v = h * Cn;
            v += __shfl_xor_sync(0xffffffffu, v, 8, 16);
            v += __shfl_xor_sync(0xffffffffu, v, 4, 16);
            v += __shfl_xor_sync(0xffffffffu, v, 2, 16);
            v += __shfl_xor_sync(0xffffffffu, v, 1, 16);
            if (l16 == 0) ys[tt][grp] = fmaf(x, Dd, v);
        }
        __syncthreads();

        if (tid < 256) {
            int r = tid >> 3, cq = (tid & 7) * 4;
            float4 yv = *(float4*)&ys[r][cq];
            float4 zv = *(float4*)&zs[r][cq];
            __nv_bfloat16 o[4];
            float zg;
            zg = zv.x / (1.f + __expf(-zv.x)); o[0] = __float2bfloat16(yv.x * zg);
            zg = zv.y / (1.f + __expf(-zv.y)); o[1] = __float2bfloat16(yv.y * zg);
            zg = zv.z / (1.f + __expf(-zv.z)); o[2] = __float2bfloat16(yv.z * zg);
            zg = zv.w / (1.f + __expf(-zv.w)); o[3] = __float2bfloat16(yv.w * zg);
            *(uint2*)(y_base + (size_t)(t0 + r) * DINNER + cq) = *(uint2*)o;
        }
    }
}

// =======================================================================
extern "C" void kernel_launch(void* const* d_in, const int* in_sizes, int n_in,
                              void* d_out, int out_size) {
    const float* hs   = (const float*)d_in[0];
    const float* nw   = (const float*)d_in[1];
    const float* inw  = (const float*)d_in[2];
    const float* cw   = (const float*)d_in[3];
    const float* cb   = (const float*)d_in[4];
    const float* xpw  = (const float*)d_in[5];
    const float* dtw  = (const float*)d_in[6];
    const float* dtb  = (const float*)d_in[7];
    const float* alog = (const float*)d_in[8];
    const float* Dp   = (const float*)d_in[9];
    const float* ow   = (const float*)d_in[10];
    float* out = (float*)d_out;

    float *p_xz, *p_xc, *p_dbl, *p_dt;
    __nv_bfloat16 *p_hb, *p_xcb, *p_dblb, *p_yb, *p_inwb, *p_xpwb, *p_dtwb, *p_owb;
    cudaGetSymbolAddress((void**)&p_xz,   g_xz);
    cudaGetSymbolAddress((void**)&p_xc,   g_xc);
    cudaGetSymbolAddress((void**)&p_dbl,  g_dbl);
    cudaGetSymbolAddress((void**)&p_dt,   g_dt);
    cudaGetSymbolAddress((void**)&p_hb,   g_hb);
    cudaGetSymbolAddress((void**)&p_xcb,  g_xcb);
    cudaGetSymbolAddress((void**)&p_dblb, g_dblb);
    cudaGetSymbolAddress((void**)&p_yb,   g_yb);
    cudaGetSymbolAddress((void**)&p_inwb, g_inwb);
    cudaGetSymbolAddress((void**)&p_xpwb, g_xpwb);
    cudaGetSymbolAddress((void**)&p_dtwb, g_dtwb);
    cudaGetSymbolAddress((void**)&p_owb,  g_owb);

    // dynamic smem: STAGES * (BM + BN) * 40 halves
    const int SM_BIG = 4 * (128 + 128) * 40 * 2;   // 81920 B
    const int SM_XP  = 4 * (64 + 32) * 40 * 2;     // 30720 B
    cudaFuncSetAttribute((const void*)k_bmma_nt<128, 128, 4, 2, 4, 0, false>,
                         cudaFuncAttributeMaxDynamicSharedMemorySize, SM_BIG);
    cudaFuncSetAttribute((const void*)k_bmma_nt<128, 128, 4, 2, 4, 1, false>,
                         cudaFuncAttributeMaxDynamicSharedMemorySize, SM_BIG);
    cudaFuncSetAttribute((const void*)k_bmma_nt<128, 128, 4, 2, 4, 2, false>,
                         cudaFuncAttributeMaxDynamicSharedMemorySize, SM_BIG);
    cudaFuncSetAttribute((const void*)k_bmma_nt<64, 32, 2, 2, 4, 0, true>,
                         cudaFuncAttributeMaxDynamicSharedMemorySize, SM_XP);

    // 0. weight conversions
    k_f2bf<<<(2 * DINNER * DMODEL / 4 + 255) / 256, 256>>>(inw, p_inwb, 2 * DINNER * DMODEL);
    k_f2bf<<<(XPOUT * DINNER / 4 + 255) / 256, 256>>>(xpw, p_xpwb, XPOUT * DINNER);
    k_f2bf<<<(DINNER * DTRANK / 4 + 255) / 256, 256>>>(dtw, p_dtwb, DINNER * DTRANK);
    k_f2bf<<<(DMODEL * DINNER / 4 + 255) / 256, 256>>>(ow, p_owb, DMODEL * DINNER);

    // 1. RMSNorm -> bf16
    k_rmsnorm<<<NTOK, 256>>>(hs, nw);

    // 2. xz = h @ in_proj_w^T   (4096 x 4096, K=1024)
    k_bmma_nt<128, 128, 4, 2, 4, 0, false><<<dim3(32, 32), 256, SM_BIG>>>(
        p_hb, DMODEL, p_inwb, DMODEL, p_xz, 2 * DINNER, DMODEL, nullptr, nullptr);

    // 3. depthwise conv + SiLU
    k_conv_silu<<<(NTOK * DINNER) / 256, 256>>>(cw, cb);

    // 4. dbl = xc @ x_proj_w^T  (4096 x 96, K=2048) -> fp32 + bf16
    k_bmma_nt<64, 32, 2, 2, 4, 0, true><<<dim3(3, 64), 128, SM_XP>>>(
        p_xcb, DINNER, p_xpwb, DINNER, p_dbl, XPOUT, DINNER, nullptr, p_dblb);

    // 5. dt = softplus(dt_r @ dt_proj_w^T + b)  (4096 x 2048, K=64)
    k_bmma_nt<128, 128, 4, 2, 4, 1, false><<<dim3(16, 32), 256, SM_BIG>>>(
        p_dblb, XPOUT, p_dtwb, DTRANK, p_dt, DINNER, DTRANK, dtb, nullptr);

    // 6. selective scan + gating -> bf16 y
    k_scan2<<<128, 512>>>(alog, Dp);

    // 7. out = y @ out_proj_w^T + residual  (4096 x 1024, K=2048)
    k_bmma_nt<128, 128, 4, 2, 4, 2, false><<<dim3(8, 32), 256, SM_BIG>>>(
        p_yb, DINNER, p_owb, DINNER, out, DMODEL, DINNER, hs, nullptr);
}